// round 7
// baseline (speedup 1.0000x reference)
#include <cuda_runtime.h>
#include <cuda_bf16.h>
#include <cstdint>

#define B_    128
#define S_    512
#define D_    2048
#define N_    128
#define NN_   16384
#define KTILE 32     /* fp32 k per tile: 128B rows -> SW128 swizzle */
#define STG   5

// ---------------- scratch (device globals; no allocation) ----------------
__device__ __align__(16) float g_mean[B_ * D_];        // 1 MB
__device__ __align__(16) float g_ctx [B_ * D_];        // 1 MB
__device__ __align__(16) float g_ctxp[2 * B_ * D_];    // 2 MB gemm1 split-K partials
__device__ __align__(16) float g_part[128 * NN_];      // 8 MB raw split-K partials
__device__ __align__(16) float g_raw [NN_];            // 64 KB

// ---------------- helpers ----------------
__device__ __forceinline__ void cp_async16(void* smem, const void* gmem) {
    uint32_t s = (uint32_t)__cvta_generic_to_shared(smem);
    asm volatile("cp.async.cg.shared.global [%0], [%1], 16;\n" :: "r"(s), "l"(gmem));
}
__device__ __forceinline__ uint32_t f2bf2(float lo, float hi) {
    uint32_t r;
    asm("cvt.rn.bf16x2.f32 %0, %1, %2;" : "=r"(r) : "f"(hi), "f"(lo));
    return r;
}
__device__ __forceinline__ void mma_bf16(float* c, const uint32_t* a, const uint32_t* b) {
    asm volatile(
        "mma.sync.aligned.m16n8k16.row.col.f32.bf16.bf16.f32 "
        "{%0,%1,%2,%3}, {%4,%5,%6,%7}, {%8,%9}, {%0,%1,%2,%3};"
        : "+f"(c[0]), "+f"(c[1]), "+f"(c[2]), "+f"(c[3])
        : "r"(a[0]), "r"(a[1]), "r"(a[2]), "r"(a[3]), "r"(b[0]), "r"(b[1]));
}

// ---------------- kernel 1: mean over sequence ----------------
__global__ void k_mean(const float4* __restrict__ x4, float4* __restrict__ m4) {
    int b  = blockIdx.x >> 3;
    int d4 = ((blockIdx.x & 7) << 6) + threadIdx.x;     // 0..511
    const float4* p = x4 + (size_t)b * (S_ * D_ / 4) + d4;
    float4 acc[8];
    #pragma unroll
    for (int u = 0; u < 8; u++) acc[u] = make_float4(0.f, 0.f, 0.f, 0.f);
    for (int s = 0; s < S_; s += 8) {
        #pragma unroll
        for (int u = 0; u < 8; u++) {
            float4 v = __ldcs(&p[(size_t)(s + u) * (D_ / 4)]);
            acc[u].x += v.x; acc[u].y += v.y; acc[u].z += v.z; acc[u].w += v.w;
        }
    }
    #pragma unroll
    for (int u = 0; u < 4; u++) {
        acc[u].x += acc[u+4].x; acc[u].y += acc[u+4].y;
        acc[u].z += acc[u+4].z; acc[u].w += acc[u+4].w;
    }
    acc[0].x += acc[2].x; acc[0].y += acc[2].y; acc[0].z += acc[2].z; acc[0].w += acc[2].w;
    acc[1].x += acc[3].x; acc[1].y += acc[3].y; acc[1].z += acc[3].z; acc[1].w += acc[3].w;
    const float inv = 1.f / (float)S_;
    float4 m;
    m.x = (acc[0].x + acc[1].x) * inv;
    m.y = (acc[0].y + acc[1].y) * inv;
    m.z = (acc[0].z + acc[1].z) * inv;
    m.w = (acc[0].w + acc[1].w) * inv;
    m4[b * (D_ / 4) + d4] = m;
}

// ---------------- swizzled cp.async 5-stage GEMM (KT=32), 256 threads, warps 4x2 ----
// smem rows are 128B (32 fp32); SW128 XOR swizzle, no padding.
// MODE 0: split-K x2 partials. grid = 2 * NFULL/NT. out[split][128][NFULL] raw acc.
// MODE 3: full-K + fused softmax/einsum/sigmoid epilogue (NT = 128).
template<int NT, int NFULL, int MODE>
__global__ void __launch_bounds__(256, 1)
k_gemm(const float* __restrict__ A, const float* __restrict__ Bm,
       const float* __restrict__ bias, float* __restrict__ out,
       const float* __restrict__ adj, const float* __restrict__ raw) {
    constexpr int ATB = 128 * 128;        // A tile bytes per stage (128 rows x 128B)
    constexpr int BTB = NT * 128;
    constexpr int NJ  = NT / 16;          // n8 tiles per warp (NT/2 cols / 8)
    constexpr int NA  = 4;                // A cp.async per thread (1024 x 16B / 256)
    constexpr int NB  = NT * 8 / 256;

    extern __shared__ __align__(1024) char smch[];
    float* sm = (float*)smch;
    char* Ab = smch;                       // [STG][A 16KB]
    char* Bb = smch + STG * ATB;           // [STG][B tile]

    const int tid  = threadIdx.x;
    const int warp = tid >> 5, lane = tid & 31;
    const int wy   = warp >> 1, wx = warp & 1;
    const int row0 = wy * 32;
    const int wxn0 = wx * (NT / 2);
    const int r    = lane >> 2, c = lane & 3;
    const uint32_t cxor = (uint32_t)r << 4;         // row&7 == r for all our rows

    int n0, k0g, nkt;
    float* op = out;
    if (MODE == 0) {
        const int nblk = NFULL / NT;
        int split = blockIdx.x / nblk;
        n0  = (blockIdx.x % nblk) * NT;
        k0g = split * (D_ / 2);
        nkt = (D_ / 2) / KTILE;            // 32
        op  = out + (size_t)split * 128 * NFULL;
    } else {
        n0 = blockIdx.x * NT; k0g = 0; nkt = D_ / KTILE;   // 64
    }

    float acc[2][NJ][4];
    #pragma unroll
    for (int m = 0; m < 2; m++)
        #pragma unroll
        for (int j = 0; j < NJ; j++)
            acc[m][j][0] = acc[m][j][1] = acc[m][j][2] = acc[m][j][3] = 0.f;

    auto issue = [&](int kt) {
        const int st = kt % STG;
        const int k0 = k0g + kt * KTILE;
        #pragma unroll
        for (int u = 0; u < NA; u++) {
            int i = tid + u * 256, rr = i >> 3;
            uint32_t cb = (uint32_t)(i & 7) * 16;
            uint32_t phys = (uint32_t)rr * 128 + (cb ^ (((uint32_t)rr & 7) << 4));
            cp_async16(Ab + st * ATB + phys, &A[(size_t)rr * D_ + k0 + (i & 7) * 4]);
        }
        #pragma unroll
        for (int u = 0; u < NB; u++) {
            int i = tid + u * 256, rr = i >> 3;
            uint32_t cb = (uint32_t)(i & 7) * 16;
            uint32_t phys = (uint32_t)rr * 128 + (cb ^ (((uint32_t)rr & 7) << 4));
            cp_async16(Bb + st * BTB + phys, &Bm[(size_t)(n0 + rr) * D_ + k0 + (i & 7) * 4]);
        }
        asm volatile("cp.async.commit_group;\n");
    };

    #pragma unroll
    for (int s = 0; s < STG - 1; s++) issue(s);

    for (int kt = 0; kt < nkt; kt++) {
        const int st = kt % STG;
        asm volatile("cp.async.wait_group %0;\n" :: "n"(STG - 2));
        __syncthreads();
        if (kt + STG - 1 < nkt) issue(kt + STG - 1);

        const char* Ast = Ab + st * ATB;
        const char* Bst = Bb + st * BTB;
        #pragma unroll
        for (int h = 0; h < 2; h++) {
            // swizzled per-lane column bytes for this h: k = h*16 + 2c (+8)
            const uint32_t c0 = ((uint32_t)(h * 64 + 8 * c)) ^ cxor;
            const uint32_t c1 = ((uint32_t)(h * 64 + 8 * c + 32)) ^ cxor;
            uint32_t a[2][4];
            #pragma unroll
            for (int m = 0; m < 2; m++) {
                const char* ap = Ast + (row0 + m * 16 + r) * 128;
                float2 v;
                v = *(const float2*)(ap + c0);          a[m][0] = f2bf2(v.x, v.y);
                v = *(const float2*)(ap + 1024 + c0);   a[m][1] = f2bf2(v.x, v.y);
                v = *(const float2*)(ap + c1);          a[m][2] = f2bf2(v.x, v.y);
                v = *(const float2*)(ap + 1024 + c1);   a[m][3] = f2bf2(v.x, v.y);
            }
            #pragma unroll
            for (int j = 0; j < NJ; j++) {
                const char* bp = Bst + (wxn0 + j * 8 + r) * 128;
                float2 v;
                uint32_t b[2];
                v = *(const float2*)(bp + c0);   b[0] = f2bf2(v.x, v.y);
                v = *(const float2*)(bp + c1);   b[1] = f2bf2(v.x, v.y);
                mma_bf16(acc[0][j], a[0], b);
                mma_bf16(acc[1][j], a[1], b);
            }
        }
        __syncthreads();
    }

    if (MODE == 0) {
        #pragma unroll
        for (int m = 0; m < 2; m++)
            #pragma unroll
            for (int j = 0; j < NJ; j++) {
                int row = row0 + m * 16 + r;
                int col = n0 + wxn0 + j * 8 + 2 * c;
                *(float2*)&op[(size_t)row * NFULL + col] =
                    make_float2(acc[m][j][0], acc[m][j][1]);
                *(float2*)&op[(size_t)(row + 8) * NFULL + col] =
                    make_float2(acc[m][j][2], acc[m][j][3]);
            }
    } else {
        // fused: logits = adj[i,:] + 0.1*(acc + bw); softmax over j; dot raw; sigmoid
        asm volatile("cp.async.wait_group 0;\n");
        __syncthreads();
        float* logit = sm;                 // [128][130]
        float* rawS  = sm + 128 * 130;     // [128][129]
        const float* adjr = adj + (size_t)blockIdx.x * 128;
        #pragma unroll
        for (int m = 0; m < 2; m++)
            #pragma unroll
            for (int j = 0; j < NJ; j++) {
                int row  = row0 + m * 16 + r;
                int lcol = wxn0 + j * 8 + 2 * c;
                int gcol = n0 + lcol;
                float b0 = bias[gcol], b1 = bias[gcol + 1];
                float a0 = adjr[lcol], a1 = adjr[lcol + 1];
                *(float2*)&logit[row * 130 + lcol] =
                    make_float2(a0 + 0.1f * (acc[m][j][0] + b0),
                                a1 + 0.1f * (acc[m][j][1] + b1));
                *(float2*)&logit[(row + 8) * 130 + lcol] =
                    make_float2(a0 + 0.1f * (acc[m][j][2] + b0),
                                a1 + 0.1f * (acc[m][j][3] + b1));
            }
        #pragma unroll
        for (int u = 0; u < 16; u++) {
            int i4 = tid + u * 256;                         // 0..4095
            float4 v = ((const float4*)raw)[i4];
            int b = i4 >> 5, j4 = (i4 & 31) * 4;
            float* d = &rawS[b * 129 + j4];
            d[0] = v.x; d[1] = v.y; d[2] = v.z; d[3] = v.w;
        }
        __syncthreads();
        if (tid < 128) {
            const float* L = &logit[tid * 130];
            const float* R = &rawS[tid * 129];
            float mx = -1e30f;
            #pragma unroll 4
            for (int j = 0; j < 128; j++) mx = fmaxf(mx, L[j]);
            float sum = 0.f, dot = 0.f;
            #pragma unroll 4
            for (int j = 0; j < 128; j++) {
                float e = __expf(L[j] - mx);
                sum += e;
                dot += e * R[j];
            }
            float w = dot / sum;
            out[(size_t)tid * N_ + blockIdx.x] = 1.f / (1.f + __expf(-w));
        }
    }
}

// ---------------- ctx reduce: ctx = p0 + p1 + bc ----------------
__global__ void k_ctxred(const float4* __restrict__ p, const float4* __restrict__ bc4,
                         float4* __restrict__ ctx4) {
    #pragma unroll
    for (int u = 0; u < 2; u++) {
        int i = blockIdx.x * 512 + threadIdx.x + u * 256;   // 0..65535 f4
        float4 a = p[i], b = p[65536 + i], c = bc4[i & 511];
        float4 o;
        o.x = a.x + b.x + c.x; o.y = a.y + b.y + c.y;
        o.z = a.z + b.z + c.z; o.w = a.w + b.w + c.w;
        ctx4[i] = o;
    }
}

// ---------------- raw-score split-K partials (fp32, deterministic) ----------------
__global__ void k_rawpart(const float* __restrict__ ctx, const float* __restrict__ rs,
                          float* __restrict__ part) {
    __shared__ float cs [128][20];
    __shared__ float rss[128][20];
    const int tid = threadIdx.x;
    const int k0  = blockIdx.x * 16;
    #pragma unroll
    for (int u = 0; u < 2; u++) {
        int i  = tid + u * 256;
        int rr = i >> 2, cc = (i & 3) * 4;
        *(float4*)&cs [rr][cc] = *(const float4*)&ctx[(size_t)rr * D_ + k0 + cc];
        *(float4*)&rss[rr][cc] = *(const float4*)&rs [(size_t)rr * D_ + k0 + cc];
    }
    __syncthreads();
    const int bb = tid >> 4;
    const int jj = tid & 15;
    float a[8][8];
    #pragma unroll
    for (int u = 0; u < 8; u++)
        #pragma unroll
        for (int v = 0; v < 8; v++) a[u][v] = 0.f;
    #pragma unroll
    for (int k = 0; k < 16; k++) {
        float cv[8], rv[8];
        #pragma unroll
        for (int u = 0; u < 8; u++) { cv[u] = cs[bb + 16*u][k]; rv[u] = rss[jj + 16*u][k]; }
        #pragma unroll
        for (int u = 0; u < 8; u++)
            #pragma unroll
            for (int v = 0; v < 8; v++) a[u][v] += cv[u] * rv[v];
    }
    float* po = part + (size_t)blockIdx.x * NN_;
    #pragma unroll
    for (int u = 0; u < 8; u++)
        #pragma unroll
        for (int v = 0; v < 8; v++)
            po[(bb + 16*u) * N_ + (jj + 16*v)] = a[u][v];
}

// ---------------- raw reduce over 128 partials ----------------
__global__ void k_rawred(const float* __restrict__ part, float* __restrict__ raw) {
    int i = blockIdx.x * 256 + threadIdx.x;   // 0..16383
    float s = 0.f;
    #pragma unroll 8
    for (int ks = 0; ks < 128; ks++) s += part[(size_t)ks * NN_ + i];
    raw[i] = s;
}

// ---------------- launch ----------------
extern "C" void kernel_launch(void* const* d_in, const int* in_sizes, int n_in,
                              void* d_out, int out_size) {
    const float* x   = (const float*)d_in[0];
    const float* rs  = (const float*)d_in[1];
    const float* Wc  = (const float*)d_in[2];
    const float* bc  = (const float*)d_in[3];
    const float* Ww  = (const float*)d_in[4];
    const float* bw  = (const float*)d_in[5];
    const float* adj = (const float*)d_in[6];
    float* out = (float*)d_out;

    float *p_mean, *p_ctx, *p_ctxp, *p_part, *p_raw;
    cudaGetSymbolAddress((void**)&p_mean, g_mean);
    cudaGetSymbolAddress((void**)&p_ctx,  g_ctx);
    cudaGetSymbolAddress((void**)&p_ctxp, g_ctxp);
    cudaGetSymbolAddress((void**)&p_part, g_part);
    cudaGetSymbolAddress((void**)&p_raw,  g_raw);

    // 1. mean over S (HBM-bound, 512 MB)
    k_mean<<<B_ * 8, 64>>>((const float4*)x, (float4*)p_mean);

    // 2. context partials: split-K x2, 128 blocks
    {
        size_t sh = (size_t)STG * (128 + 32) * 128;
        cudaFuncSetAttribute((const void*)k_gemm<32, D_, 0>,
                             cudaFuncAttributeMaxDynamicSharedMemorySize, (int)sh);
        k_gemm<32, D_, 0><<<128, 256, sh>>>(p_mean, Wc, nullptr, p_ctxp, nullptr, nullptr);
    }
    // 2b. ctx = p0 + p1 + bc
    k_ctxred<<<128, 256>>>((const float4*)p_ctxp, (const float4*)bc, (float4*)p_ctx);

    // 3. raw = ctx @ rs^T (split-K partials + reduce)
    k_rawpart<<<128, 256>>>(p_ctx, rs, p_part);
    k_rawred<<<64, 256>>>(p_part, p_raw);

    // 4+5. warp GEMM + fused softmax/einsum/sigmoid
    {
        size_t sh = (size_t)STG * (128 + 128) * 128;
        cudaFuncSetAttribute((const void*)k_gemm<128, NN_, 3>,
                             cudaFuncAttributeMaxDynamicSharedMemorySize, (int)sh);
        k_gemm<128, NN_, 3><<<128, 256, sh>>>(p_ctx, Ww, bw, out, adj, p_raw);
    }
}

// round 8
// speedup vs baseline: 1.1348x; 1.1348x over previous
#include <cuda_runtime.h>
#include <cuda_bf16.h>
#include <cstdint>

#define B_    128
#define S_    512
#define D_    2048
#define N_    128
#define NN_   16384
#define KTILE 64
#define SBW   144    /* bf16 tile row stride bytes: 128 data + 16 pad (conflict-free) */
#define STG   3
#define ASTG  (128 * SBW)

// ---------------- scratch (device globals; no allocation) ----------------
__device__ __align__(16) float g_mean[B_ * D_];        // 1 MB
__device__ __align__(16) float g_ctx [B_ * D_];        // 1 MB
__device__ __align__(16) float g_ctxp[2 * B_ * D_];    // 2 MB gemm1 split-K partials
__device__ __align__(16) float g_part[128 * NN_];      // 8 MB raw split-K partials
__device__ __align__(16) float g_raw [NN_];            // 64 KB

// ---------------- helpers ----------------
__device__ __forceinline__ uint32_t f2bf2(float lo, float hi) {
    uint32_t r;
    asm("cvt.rn.bf16x2.f32 %0, %1, %2;" : "=r"(r) : "f"(hi), "f"(lo));  // hi -> upper 16
    return r;
}
__device__ __forceinline__ void mma_bf16(float* c, const uint32_t* a, const uint32_t* b) {
    asm volatile(
        "mma.sync.aligned.m16n8k16.row.col.f32.bf16.bf16.f32 "
        "{%0,%1,%2,%3}, {%4,%5,%6,%7}, {%8,%9}, {%0,%1,%2,%3};"
        : "+f"(c[0]), "+f"(c[1]), "+f"(c[2]), "+f"(c[3])
        : "r"(a[0]), "r"(a[1]), "r"(a[2]), "r"(a[3]), "r"(b[0]), "r"(b[1]));
}

// ---------------- kernel 1: mean over sequence ----------------
__global__ void k_mean(const float4* __restrict__ x4, float4* __restrict__ m4) {
    int b  = blockIdx.x >> 3;
    int d4 = ((blockIdx.x & 7) << 6) + threadIdx.x;     // 0..511
    const float4* p = x4 + (size_t)b * (S_ * D_ / 4) + d4;
    float4 acc[8];
    #pragma unroll
    for (int u = 0; u < 8; u++) acc[u] = make_float4(0.f, 0.f, 0.f, 0.f);
    for (int s = 0; s < S_; s += 8) {
        #pragma unroll
        for (int u = 0; u < 8; u++) {
            float4 v = __ldcs(&p[(size_t)(s + u) * (D_ / 4)]);
            acc[u].x += v.x; acc[u].y += v.y; acc[u].z += v.z; acc[u].w += v.w;
        }
    }
    #pragma unroll
    for (int u = 0; u < 4; u++) {
        acc[u].x += acc[u+4].x; acc[u].y += acc[u+4].y;
        acc[u].z += acc[u+4].z; acc[u].w += acc[u+4].w;
    }
    acc[0].x += acc[2].x; acc[0].y += acc[2].y; acc[0].z += acc[2].z; acc[0].w += acc[2].w;
    acc[1].x += acc[3].x; acc[1].y += acc[3].y; acc[1].z += acc[3].z; acc[1].w += acc[3].w;
    const float inv = 1.f / (float)S_;
    float4 m;
    m.x = (acc[0].x + acc[1].x) * inv;
    m.y = (acc[0].y + acc[1].y) * inv;
    m.z = (acc[0].z + acc[1].z) * inv;
    m.w = (acc[0].w + acc[1].w) * inv;
    m4[b * (D_ / 4) + d4] = m;
}

// ---------------- bf16-smem GEMM (KT=64), 256 threads, warps 4x2, 3-stage ring ----
// Producers: LDG fp32 -> cvt bf16 -> STS.128 into 144B-stride tiles (1 iter of reg staging).
// Consumers: LDS.32 fragments (conflict-free) + mma.m16n8k16.
// MODE 0: split-K x2 partials. grid = 2 * NFULL/NT. out[split][128][NFULL] raw acc.
// MODE 3: full-K + fused softmax/einsum/sigmoid epilogue (NT = 128).
template<int NT, int NFULL, int MODE>
__global__ void __launch_bounds__(256, 1)
k_gemm(const float* __restrict__ A, const float* __restrict__ Bm,
       const float* __restrict__ bias, float* __restrict__ out,
       const float* __restrict__ adj, const float* __restrict__ raw) {
    constexpr int BTB = NT * SBW;        // B tile bytes per stage
    constexpr int NJ  = NT / 16;         // n8 tiles per warp (NT/2 cols / 8)
    constexpr int NAS = 4;               // A slots per thread (128*8/256)
    constexpr int NBS = NT * 8 / 256;    // B slots per thread

    extern __shared__ __align__(16) char smch[];
    float* sm = (float*)smch;
    char* Ab = smch;                      // [STG][128][SBW]
    char* Bb = smch + STG * ASTG;         // [STG][NT ][SBW]

    const int tid  = threadIdx.x;
    const int warp = tid >> 5, lane = tid & 31;
    const int wy   = warp >> 1, wx = warp & 1;
    const int row0 = wy * 32;
    const int wxn0 = wx * (NT / 2);
    const int r    = lane >> 2, c = lane & 3;

    int n0, k0g, nkt;
    float* op = out;
    if (MODE == 0) {
        const int nblk = NFULL / NT;
        int split = blockIdx.x / nblk;
        n0  = (blockIdx.x % nblk) * NT;
        k0g = split * (D_ / 2);
        nkt = (D_ / 2) / KTILE;           // 16
        op  = out + (size_t)split * 128 * NFULL;
    } else {
        n0 = blockIdx.x * NT; k0g = 0; nkt = D_ / KTILE;   // 32
    }

    float acc[2][NJ][4];
    #pragma unroll
    for (int m = 0; m < 2; m++)
        #pragma unroll
        for (int j = 0; j < NJ; j++)
            acc[m][j][0] = acc[m][j][1] = acc[m][j][2] = acc[m][j][3] = 0.f;

    // register staging: one tile (A + B slots, 2 float4 each)
    float4 vA[NAS][2], vB[NBS][2];

    auto ldgreg = [&](int kt) {
        const int k0 = k0g + kt * KTILE;
        #pragma unroll
        for (int u = 0; u < NAS; u++) {
            int s = tid + u * 256, row = s >> 3, c8 = s & 7;
            const float* p = &A[(size_t)row * D_ + k0 + c8 * 8];
            vA[u][0] = *(const float4*)(p);
            vA[u][1] = *(const float4*)(p + 4);
        }
        #pragma unroll
        for (int u = 0; u < NBS; u++) {
            int s = tid + u * 256, row = s >> 3, c8 = s & 7;
            const float* p = &Bm[(size_t)(n0 + row) * D_ + k0 + c8 * 8];
            vB[u][0] = *(const float4*)(p);
            vB[u][1] = *(const float4*)(p + 4);
        }
    };
    auto sts = [&](int st) {
        #pragma unroll
        for (int u = 0; u < NAS; u++) {
            int s = tid + u * 256, row = s >> 3, c8 = s & 7;
            uint4 pk = make_uint4(f2bf2(vA[u][0].x, vA[u][0].y), f2bf2(vA[u][0].z, vA[u][0].w),
                                  f2bf2(vA[u][1].x, vA[u][1].y), f2bf2(vA[u][1].z, vA[u][1].w));
            *(uint4*)(Ab + st * ASTG + row * SBW + c8 * 16) = pk;
        }
        #pragma unroll
        for (int u = 0; u < NBS; u++) {
            int s = tid + u * 256, row = s >> 3, c8 = s & 7;
            uint4 pk = make_uint4(f2bf2(vB[u][0].x, vB[u][0].y), f2bf2(vB[u][0].z, vB[u][0].w),
                                  f2bf2(vB[u][1].x, vB[u][1].y), f2bf2(vB[u][1].z, vB[u][1].w));
            *(uint4*)(Bb + st * BTB + row * SBW + c8 * 16) = pk;
        }
    };

    // prologue: stages 0,1 filled; regs hold tile 2
    ldgreg(0); sts(0);
    ldgreg(1); sts(1);
    ldgreg(2);
    __syncthreads();

    for (int kt = 0; kt < nkt; kt++) {
        const int st = kt % STG;
        if (kt + 2 < nkt) sts((kt + 2) % STG);
        if (kt + 3 < nkt) ldgreg(kt + 3);

        const char* Ast = Ab + st * ASTG;
        const char* Bst = Bb + st * BTB;
        #pragma unroll
        for (int h = 0; h < 4; h++) {
            const int cb = h * 32 + 4 * c;            // byte offset of k=(16h+2c) bf16 pair
            uint32_t a[2][4];
            #pragma unroll
            for (int m = 0; m < 2; m++) {
                const char* ap = Ast + (row0 + m * 16 + r) * SBW;
                a[m][0] = *(const uint32_t*)(ap + cb);
                a[m][1] = *(const uint32_t*)(ap + 8 * SBW + cb);
                a[m][2] = *(const uint32_t*)(ap + cb + 16);
                a[m][3] = *(const uint32_t*)(ap + 8 * SBW + cb + 16);
            }
            #pragma unroll
            for (int j = 0; j < NJ; j++) {
                const char* bp = Bst + (wxn0 + j * 8 + r) * SBW;
                uint32_t b[2];
                b[0] = *(const uint32_t*)(bp + cb);
                b[1] = *(const uint32_t*)(bp + cb + 16);
                mma_bf16(acc[0][j], a[0], b);
                mma_bf16(acc[1][j], a[1], b);
            }
        }
        __syncthreads();
    }

    if (MODE == 0) {
        #pragma unroll
        for (int m = 0; m < 2; m++)
            #pragma unroll
            for (int j = 0; j < NJ; j++) {
                int row = row0 + m * 16 + r;
                int col = n0 + wxn0 + j * 8 + 2 * c;
                *(float2*)&op[(size_t)row * NFULL + col] =
                    make_float2(acc[m][j][0], acc[m][j][1]);
                *(float2*)&op[(size_t)(row + 8) * NFULL + col] =
                    make_float2(acc[m][j][2], acc[m][j][3]);
            }
    } else {
        // fused: logits = adj[i,:] + 0.1*(acc + bw); softmax over j; dot raw; sigmoid
        float* logit = sm;                 // [128][130]
        float* rawS  = sm + 128 * 130;     // [128][129]
        const float* adjr = adj + (size_t)blockIdx.x * 128;
        #pragma unroll
        for (int m = 0; m < 2; m++)
            #pragma unroll
            for (int j = 0; j < NJ; j++) {
                int row  = row0 + m * 16 + r;
                int lcol = wxn0 + j * 8 + 2 * c;
                int gcol = n0 + lcol;
                float b0 = bias[gcol], b1 = bias[gcol + 1];
                float a0 = adjr[lcol], a1 = adjr[lcol + 1];
                *(float2*)&logit[row * 130 + lcol] =
                    make_float2(a0 + 0.1f * (acc[m][j][0] + b0),
                                a1 + 0.1f * (acc[m][j][1] + b1));
                *(float2*)&logit[(row + 8) * 130 + lcol] =
                    make_float2(a0 + 0.1f * (acc[m][j][2] + b0),
                                a1 + 0.1f * (acc[m][j][3] + b1));
            }
        #pragma unroll
        for (int u = 0; u < 16; u++) {
            int i4 = tid + u * 256;                         // 0..4095
            float4 v = ((const float4*)raw)[i4];
            int b = i4 >> 5, j4 = (i4 & 31) * 4;
            float* d = &rawS[b * 129 + j4];
            d[0] = v.x; d[1] = v.y; d[2] = v.z; d[3] = v.w;
        }
        __syncthreads();
        if (tid < 128) {
            const float* L = &logit[tid * 130];
            const float* R = &rawS[tid * 129];
            float mx = -1e30f;
            #pragma unroll 4
            for (int j = 0; j < 128; j++) mx = fmaxf(mx, L[j]);
            float sum = 0.f, dot = 0.f;
            #pragma unroll 4
            for (int j = 0; j < 128; j++) {
                float e = __expf(L[j] - mx);
                sum += e;
                dot += e * R[j];
            }
            float w = dot / sum;
            out[(size_t)tid * N_ + blockIdx.x] = 1.f / (1.f + __expf(-w));
        }
    }
}

// ---------------- ctx reduce: ctx = p0 + p1 + bc ----------------
__global__ void k_ctxred(const float4* __restrict__ p, const float4* __restrict__ bc4,
                         float4* __restrict__ ctx4) {
    #pragma unroll
    for (int u = 0; u < 2; u++) {
        int i = blockIdx.x * 512 + threadIdx.x + u * 256;   // 0..65535 f4
        float4 a = p[i], b = p[65536 + i], c = bc4[i & 511];
        float4 o;
        o.x = a.x + b.x + c.x; o.y = a.y + b.y + c.y;
        o.z = a.z + b.z + c.z; o.w = a.w + b.w + c.w;
        ctx4[i] = o;
    }
}

// ---------------- raw-score split-K partials (fp32, deterministic) ----------------
__global__ void k_rawpart(const float* __restrict__ ctx, const float* __restrict__ rs,
                          float* __restrict__ part) {
    __shared__ float cs [128][20];
    __shared__ float rss[128][20];
    const int tid = threadIdx.x;
    const int k0  = blockIdx.x * 16;
    #pragma unroll
    for (int u = 0; u < 2; u++) {
        int i  = tid + u * 256;
        int rr = i >> 2, cc = (i & 3) * 4;
        *(float4*)&cs [rr][cc] = *(const float4*)&ctx[(size_t)rr * D_ + k0 + cc];
        *(float4*)&rss[rr][cc] = *(const float4*)&rs [(size_t)rr * D_ + k0 + cc];
    }
    __syncthreads();
    const int bb = tid >> 4;
    const int jj = tid & 15;
    float a[8][8];
    #pragma unroll
    for (int u = 0; u < 8; u++)
        #pragma unroll
        for (int v = 0; v < 8; v++) a[u][v] = 0.f;
    #pragma unroll
    for (int k = 0; k < 16; k++) {
        float cv[8], rv[8];
        #pragma unroll
        for (int u = 0; u < 8; u++) { cv[u] = cs[bb + 16*u][k]; rv[u] = rss[jj + 16*u][k]; }
        #pragma unroll
        for (int u = 0; u < 8; u++)
            #pragma unroll
            for (int v = 0; v < 8; v++) a[u][v] += cv[u] * rv[v];
    }
    float* po = part + (size_t)blockIdx.x * NN_;
    #pragma unroll
    for (int u = 0; u < 8; u++)
        #pragma unroll
        for (int v = 0; v < 8; v++)
            po[(bb + 16*u) * N_ + (jj + 16*v)] = a[u][v];
}

// ---------------- raw reduce over 128 partials ----------------
__global__ void k_rawred(const float* __restrict__ part, float* __restrict__ raw) {
    int i = blockIdx.x * 256 + threadIdx.x;   // 0..16383
    float s = 0.f;
    #pragma unroll 8
    for (int ks = 0; ks < 128; ks++) s += part[(size_t)ks * NN_ + i];
    raw[i] = s;
}

// ---------------- launch ----------------
extern "C" void kernel_launch(void* const* d_in, const int* in_sizes, int n_in,
                              void* d_out, int out_size) {
    const float* x   = (const float*)d_in[0];
    const float* rs  = (const float*)d_in[1];
    const float* Wc  = (const float*)d_in[2];
    const float* bc  = (const float*)d_in[3];
    const float* Ww  = (const float*)d_in[4];
    const float* bw  = (const float*)d_in[5];
    const float* adj = (const float*)d_in[6];
    float* out = (float*)d_out;

    float *p_mean, *p_ctx, *p_ctxp, *p_part, *p_raw;
    cudaGetSymbolAddress((void**)&p_mean, g_mean);
    cudaGetSymbolAddress((void**)&p_ctx,  g_ctx);
    cudaGetSymbolAddress((void**)&p_ctxp, g_ctxp);
    cudaGetSymbolAddress((void**)&p_part, g_part);
    cudaGetSymbolAddress((void**)&p_raw,  g_raw);

    // 1. mean over S (HBM-bound, 512 MB)
    k_mean<<<B_ * 8, 64>>>((const float4*)x, (float4*)p_mean);

    // 2. context partials: split-K x2, 128 blocks
    {
        size_t sh = (size_t)STG * (128 + 32) * SBW;     // 69,120 B
        cudaFuncSetAttribute((const void*)k_gemm<32, D_, 0>,
                             cudaFuncAttributeMaxDynamicSharedMemorySize, (int)sh);
        k_gemm<32, D_, 0><<<128, 256, sh>>>(p_mean, Wc, nullptr, p_ctxp, nullptr, nullptr);
    }
    // 2b. ctx = p0 + p1 + bc
    k_ctxred<<<128, 256>>>((const float4*)p_ctxp, (const float4*)bc, (float4*)p_ctx);

    // 3. raw = ctx @ rs^T (split-K partials + reduce)
    k_rawpart<<<128, 256>>>(p_ctx, rs, p_part);
    k_rawred<<<64, 256>>>(p_part, p_raw);

    // 4+5. warp GEMM + fused softmax/einsum/sigmoid
    {
        size_t stages = (size_t)STG * (128 + 128) * SBW;            // 110,592 B
        size_t epi    = (size_t)(128 * 130 + 128 * 129) * 4;        // 132,608 B
        size_t sh     = stages > epi ? stages : epi;
        cudaFuncSetAttribute((const void*)k_gemm<128, NN_, 3>,
                             cudaFuncAttributeMaxDynamicSharedMemorySize, (int)sh);
        k_gemm<128, NN_, 3><<<128, 256, sh>>>(p_ctx, Ww, bw, out, adj, p_raw);
    }
}

// round 9
// speedup vs baseline: 1.2103x; 1.0665x over previous
#include <cuda_runtime.h>
#include <cuda_bf16.h>
#include <cstdint>

#define B_    128
#define S_    512
#define D_    2048
#define N_    128
#define NN_   16384
#define KTILE 64
#define ABW   144    /* A (bf16) smem row stride bytes: 128 data + 16 pad */
#define BPAD  72     /* B (fp32) smem row stride floats: 64 data + 8 pad */
#define STG   3
#define ATB   (128 * ABW)

// ---------------- scratch (device globals; no allocation) ----------------
__device__ __align__(16) __nv_bfloat16 g_meanbf[B_ * D_];  // 0.5 MB
__device__ __align__(16) float g_ctx [B_ * D_];            // 1 MB (fp32, for rawpart)
__device__ __align__(16) __nv_bfloat16 g_ctxbf[B_ * D_];   // 0.5 MB (bf16, gemm2 A)
__device__ __align__(16) float g_ctxp[2 * B_ * D_];        // 2 MB gemm1 split-K partials
__device__ __align__(16) float g_part[128 * NN_];          // 8 MB raw split-K partials
__device__ __align__(16) float g_raw [NN_];                // 64 KB

// ---------------- helpers ----------------
__device__ __forceinline__ void cp_async16(void* smem, const void* gmem) {
    uint32_t s = (uint32_t)__cvta_generic_to_shared(smem);
    asm volatile("cp.async.cg.shared.global [%0], [%1], 16;\n" :: "r"(s), "l"(gmem));
}
__device__ __forceinline__ uint32_t f2bf2(float lo, float hi) {
    uint32_t r;
    asm("cvt.rn.bf16x2.f32 %0, %1, %2;" : "=r"(r) : "f"(hi), "f"(lo));  // hi -> upper 16
    return r;
}
__device__ __forceinline__ void mma_bf16(float* c, const uint32_t* a, const uint32_t* b) {
    asm volatile(
        "mma.sync.aligned.m16n8k16.row.col.f32.bf16.bf16.f32 "
        "{%0,%1,%2,%3}, {%4,%5,%6,%7}, {%8,%9}, {%0,%1,%2,%3};"
        : "+f"(c[0]), "+f"(c[1]), "+f"(c[2]), "+f"(c[3])
        : "r"(a[0]), "r"(a[1]), "r"(a[2]), "r"(a[3]), "r"(b[0]), "r"(b[1]));
}

// ---------------- kernel 1: mean over sequence -> bf16 ----------------
__global__ void k_mean(const float4* __restrict__ x4, uint2* __restrict__ mbf) {
    int b  = blockIdx.x >> 3;
    int d4 = ((blockIdx.x & 7) << 6) + threadIdx.x;     // 0..511
    const float4* p = x4 + (size_t)b * (S_ * D_ / 4) + d4;
    float4 acc[8];
    #pragma unroll
    for (int u = 0; u < 8; u++) acc[u] = make_float4(0.f, 0.f, 0.f, 0.f);
    for (int s = 0; s < S_; s += 8) {
        #pragma unroll
        for (int u = 0; u < 8; u++) {
            float4 v = __ldcs(&p[(size_t)(s + u) * (D_ / 4)]);
            acc[u].x += v.x; acc[u].y += v.y; acc[u].z += v.z; acc[u].w += v.w;
        }
    }
    #pragma unroll
    for (int u = 0; u < 4; u++) {
        acc[u].x += acc[u+4].x; acc[u].y += acc[u+4].y;
        acc[u].z += acc[u+4].z; acc[u].w += acc[u+4].w;
    }
    acc[0].x += acc[2].x; acc[0].y += acc[2].y; acc[0].z += acc[2].z; acc[0].w += acc[2].w;
    acc[1].x += acc[3].x; acc[1].y += acc[3].y; acc[1].z += acc[3].z; acc[1].w += acc[3].w;
    const float inv = 1.f / (float)S_;
    float mx = (acc[0].x + acc[1].x) * inv;
    float my = (acc[0].y + acc[1].y) * inv;
    float mz = (acc[0].z + acc[1].z) * inv;
    float mw = (acc[0].w + acc[1].w) * inv;
    mbf[b * (D_ / 4) + d4] = make_uint2(f2bf2(mx, my), f2bf2(mz, mw));
}

// ---------------- cp.async 3-stage GEMM: A bf16-smem, B fp32-smem ----------------
// out[128, NFULL] = A[128,2048] @ Bm[NFULL,2048]^T; NT cols per block.
// 256 threads = 8 warps as 2(M: 64-row groups) x 4(N: NT/4 quarters).
// MODE 0: split-K x2 partials. grid = 2 * NFULL/NT. out[split][128][NFULL] raw acc.
// MODE 3: full-K + fused softmax/einsum/sigmoid epilogue (NT = 128).
template<int NT, int NFULL, int MODE>
__global__ void __launch_bounds__(256, 1)
k_gemm(const __nv_bfloat16* __restrict__ Abf, const float* __restrict__ Bm,
       const float* __restrict__ bias, float* __restrict__ out,
       const float* __restrict__ adj, const float* __restrict__ raw) {
    constexpr int BTB = NT * BPAD * 4;   // B tile bytes per stage
    constexpr int NJ  = NT / 32;         // n8 tiles per warp (NT/4 cols / 8)
    constexpr int NAC = 4;               // A cp.async per thread (128*8/256)
    constexpr int NBC = NT * 16 / 256;   // B cp.async per thread

    extern __shared__ __align__(16) char smch[];
    float* sm = (float*)smch;
    char* Ab = smch;                      // [STG][128][ABW]
    char* Bb = smch + STG * ATB;          // [STG][NT][BPAD*4]

    const int tid  = threadIdx.x;
    const int warp = tid >> 5, lane = tid & 31;
    const int wy   = warp >> 2, wx = warp & 3;
    const int row0 = wy * 64;
    const int wxn0 = wx * (NT / 4);
    const int r    = lane >> 2, c = lane & 3;

    int n0, k0g, nkt;
    float* op = out;
    if (MODE == 0) {
        const int nblk = NFULL / NT;
        int split = blockIdx.x / nblk;
        n0  = (blockIdx.x % nblk) * NT;
        k0g = split * (D_ / 2);
        nkt = (D_ / 2) / KTILE;           // 16
        op  = out + (size_t)split * 128 * NFULL;
    } else {
        n0 = blockIdx.x * NT; k0g = 0; nkt = D_ / KTILE;   // 32
    }

    float acc[4][NJ][4];
    #pragma unroll
    for (int m = 0; m < 4; m++)
        #pragma unroll
        for (int j = 0; j < NJ; j++)
            acc[m][j][0] = acc[m][j][1] = acc[m][j][2] = acc[m][j][3] = 0.f;

    auto issue = [&](int kt) {
        const int st = kt % STG;
        const int k0 = k0g + kt * KTILE;
        #pragma unroll
        for (int u = 0; u < NAC; u++) {               // A: 128 rows x 64 bf16 (8 x 16B)
            int i = tid + u * 256, rr = i >> 3, c8 = i & 7;
            cp_async16(Ab + st * ATB + rr * ABW + c8 * 16,
                       &Abf[(size_t)rr * D_ + k0 + c8 * 8]);
        }
        #pragma unroll
        for (int u = 0; u < NBC; u++) {               // B: NT rows x 64 fp32 (16 x 16B)
            int i = tid + u * 256, rr = i >> 4, c16 = i & 15;
            cp_async16(Bb + st * BTB + rr * (BPAD * 4) + c16 * 16,
                       &Bm[(size_t)(n0 + rr) * D_ + k0 + c16 * 4]);
        }
        asm volatile("cp.async.commit_group;\n");
    };

    issue(0);
    issue(1);

    for (int kt = 0; kt < nkt; kt++) {
        const int st = kt % STG;
        asm volatile("cp.async.wait_group 1;\n");
        __syncthreads();
        if (kt + 2 < nkt) issue(kt + 2);
        else asm volatile("cp.async.commit_group;\n");

        const char*  Ast = Ab + st * ATB;
        const float* Bst = (const float*)(Bb + st * BTB);
        #pragma unroll
        for (int h = 0; h < 4; h++) {
            const int cb = h * 32 + 4 * c;            // A byte offset of k = 16h + 2c
            const int kb = h * 16 + 2 * c;            // B float offset
            uint32_t a[4][4];
            #pragma unroll
            for (int m = 0; m < 4; m++) {
                const char* ap = Ast + (row0 + m * 16 + r) * ABW;
                a[m][0] = *(const uint32_t*)(ap + cb);
                a[m][1] = *(const uint32_t*)(ap + 8 * ABW + cb);
                a[m][2] = *(const uint32_t*)(ap + cb + 16);
                a[m][3] = *(const uint32_t*)(ap + 8 * ABW + cb + 16);
            }
            #pragma unroll
            for (int j = 0; j < NJ; j++) {
                const float* bp = Bst + (wxn0 + j * 8 + r) * BPAD + kb;
                float2 v;
                uint32_t b[2];
                v = *(const float2*)(bp);       b[0] = f2bf2(v.x, v.y);
                v = *(const float2*)(bp + 8);   b[1] = f2bf2(v.x, v.y);
                #pragma unroll
                for (int m = 0; m < 4; m++) mma_bf16(acc[m][j], a[m], b);
            }
        }
        __syncthreads();
    }

    if (MODE == 0) {
        #pragma unroll
        for (int m = 0; m < 4; m++)
            #pragma unroll
            for (int j = 0; j < NJ; j++) {
                int row = row0 + m * 16 + r;
                int col = n0 + wxn0 + j * 8 + 2 * c;
                *(float2*)&op[(size_t)row * NFULL + col] =
                    make_float2(acc[m][j][0], acc[m][j][1]);
                *(float2*)&op[(size_t)(row + 8) * NFULL + col] =
                    make_float2(acc[m][j][2], acc[m][j][3]);
            }
    } else {
        // fused: logits = adj[i,:] + 0.1*(acc + bw); softmax over j; dot raw; sigmoid
        asm volatile("cp.async.wait_group 0;\n");
        __syncthreads();
        float* logit = sm;                 // [128][130]
        float* rawS  = sm + 128 * 130;     // [128][129]
        const float* adjr = adj + (size_t)blockIdx.x * 128;
        #pragma unroll
        for (int m = 0; m < 4; m++)
            #pragma unroll
            for (int j = 0; j < NJ; j++) {
                int row  = row0 + m * 16 + r;
                int lcol = wxn0 + j * 8 + 2 * c;
                int gcol = n0 + lcol;
                float b0 = bias[gcol], b1 = bias[gcol + 1];
                float a0 = adjr[lcol], a1 = adjr[lcol + 1];
                *(float2*)&logit[row * 130 + lcol] =
                    make_float2(a0 + 0.1f * (acc[m][j][0] + b0),
                                a1 + 0.1f * (acc[m][j][1] + b1));
                *(float2*)&logit[(row + 8) * 130 + lcol] =
                    make_float2(a0 + 0.1f * (acc[m][j][2] + b0),
                                a1 + 0.1f * (acc[m][j][3] + b1));
            }
        #pragma unroll
        for (int u = 0; u < 16; u++) {
            int i4 = tid + u * 256;                         // 0..4095
            float4 v = ((const float4*)raw)[i4];
            int b = i4 >> 5, j4 = (i4 & 31) * 4;
            float* d = &rawS[b * 129 + j4];
            d[0] = v.x; d[1] = v.y; d[2] = v.z; d[3] = v.w;
        }
        __syncthreads();
        if (tid < 128) {
            const float* L = &logit[tid * 130];
            const float* R = &rawS[tid * 129];
            float mx = -1e30f;
            #pragma unroll 4
            for (int j = 0; j < 128; j++) mx = fmaxf(mx, L[j]);
            float sum = 0.f, dot = 0.f;
            #pragma unroll 4
            for (int j = 0; j < 128; j++) {
                float e = __expf(L[j] - mx);
                sum += e;
                dot += e * R[j];
            }
            float w = dot / sum;
            out[(size_t)tid * N_ + blockIdx.x] = 1.f / (1.f + __expf(-w));
        }
    }
}

// ---------------- ctx reduce: ctx = p0 + p1 + bc (fp32 + bf16 copies) ----------------
__global__ void k_ctxred(const float4* __restrict__ p, const float4* __restrict__ bc4,
                         float4* __restrict__ ctx4, uint2* __restrict__ ctxbf) {
    #pragma unroll
    for (int u = 0; u < 2; u++) {
        int i = blockIdx.x * 512 + threadIdx.x + u * 256;   // 0..65535 f4
        float4 a = p[i], b = p[65536 + i], c = bc4[i & 511];
        float4 o;
        o.x = a.x + b.x + c.x; o.y = a.y + b.y + c.y;
        o.z = a.z + b.z + c.z; o.w = a.w + b.w + c.w;
        ctx4[i] = o;
        ctxbf[i] = make_uint2(f2bf2(o.x, o.y), f2bf2(o.z, o.w));
    }
}

// ---------------- raw-score split-K partials (fp32, deterministic) ----------------
__global__ void k_rawpart(const float* __restrict__ ctx, const float* __restrict__ rs,
                          float* __restrict__ part) {
    __shared__ float cs [128][20];
    __shared__ float rss[128][20];
    const int tid = threadIdx.x;
    const int k0  = blockIdx.x * 16;
    #pragma unroll
    for (int u = 0; u < 2; u++) {
        int i  = tid + u * 256;
        int rr = i >> 2, cc = (i & 3) * 4;
        *(float4*)&cs [rr][cc] = *(const float4*)&ctx[(size_t)rr * D_ + k0 + cc];
        *(float4*)&rss[rr][cc] = *(const float4*)&rs [(size_t)rr * D_ + k0 + cc];
    }
    __syncthreads();
    const int bb = tid >> 4;
    const int jj = tid & 15;
    float a[8][8];
    #pragma unroll
    for (int u = 0; u < 8; u++)
        #pragma unroll
        for (int v = 0; v < 8; v++) a[u][v] = 0.f;
    #pragma unroll
    for (int k = 0; k < 16; k++) {
        float cv[8], rv[8];
        #pragma unroll
        for (int u = 0; u < 8; u++) { cv[u] = cs[bb + 16*u][k]; rv[u] = rss[jj + 16*u][k]; }
        #pragma unroll
        for (int u = 0; u < 8; u++)
            #pragma unroll
            for (int v = 0; v < 8; v++) a[u][v] += cv[u] * rv[v];
    }
    float* po = part + (size_t)blockIdx.x * NN_;
    #pragma unroll
    for (int u = 0; u < 8; u++)
        #pragma unroll
        for (int v = 0; v < 8; v++)
            po[(bb + 16*u) * N_ + (jj + 16*v)] = a[u][v];
}

// ---------------- raw reduce over 128 partials ----------------
__global__ void k_rawred(const float* __restrict__ part, float* __restrict__ raw) {
    int i = blockIdx.x * 256 + threadIdx.x;   // 0..16383
    float s = 0.f;
    #pragma unroll 8
    for (int ks = 0; ks < 128; ks++) s += part[(size_t)ks * NN_ + i];
    raw[i] = s;
}

// ---------------- launch ----------------
extern "C" void kernel_launch(void* const* d_in, const int* in_sizes, int n_in,
                              void* d_out, int out_size) {
    const float* x   = (const float*)d_in[0];
    const float* rs  = (const float*)d_in[1];
    const float* Wc  = (const float*)d_in[2];
    const float* bc  = (const float*)d_in[3];
    const float* Ww  = (const float*)d_in[4];
    const float* bw  = (const float*)d_in[5];
    const float* adj = (const float*)d_in[6];
    float* out = (float*)d_out;

    __nv_bfloat16 *p_meanbf, *p_ctxbf;
    float *p_ctx, *p_ctxp, *p_part, *p_raw;
    cudaGetSymbolAddress((void**)&p_meanbf, g_meanbf);
    cudaGetSymbolAddress((void**)&p_ctx,   g_ctx);
    cudaGetSymbolAddress((void**)&p_ctxbf, g_ctxbf);
    cudaGetSymbolAddress((void**)&p_ctxp,  g_ctxp);
    cudaGetSymbolAddress((void**)&p_part,  g_part);
    cudaGetSymbolAddress((void**)&p_raw,   g_raw);

    // 1. mean over S (HBM-bound, 512 MB) -> bf16
    k_mean<<<B_ * 8, 64>>>((const float4*)x, (uint2*)p_meanbf);

    // 2. context partials: split-K x2, 128 blocks
    {
        size_t sh = (size_t)STG * (ATB / 128 * 128 + 32 * BPAD * 4);   // 3*(18432+9216)
        cudaFuncSetAttribute((const void*)k_gemm<32, D_, 0>,
                             cudaFuncAttributeMaxDynamicSharedMemorySize, (int)sh);
        k_gemm<32, D_, 0><<<128, 256, sh>>>(p_meanbf, Wc, nullptr, p_ctxp, nullptr, nullptr);
    }
    // 2b. ctx = p0 + p1 + bc (fp32 + bf16)
    k_ctxred<<<128, 256>>>((const float4*)p_ctxp, (const float4*)bc,
                           (float4*)p_ctx, (uint2*)p_ctxbf);

    // 3. raw = ctx @ rs^T (split-K partials + reduce)
    k_rawpart<<<128, 256>>>(p_ctx, rs, p_part);
    k_rawred<<<64, 256>>>(p_part, p_raw);

    // 4+5. warp GEMM + fused softmax/einsum/sigmoid
    {
        size_t stages = (size_t)STG * (ATB + 128 * BPAD * 4);          // 165,888 B
        size_t epi    = (size_t)(128 * 130 + 128 * 129) * 4;           // 132,608 B
        size_t sh     = stages > epi ? stages : epi;
        cudaFuncSetAttribute((const void*)k_gemm<128, NN_, 3>,
                             cudaFuncAttributeMaxDynamicSharedMemorySize, (int)sh);
        k_gemm<128, NN_, 3><<<128, 256, sh>>>(p_ctxbf, Ww, bw, out, adj, p_raw);
    }
}

// round 10
// speedup vs baseline: 1.2323x; 1.0182x over previous
#include <cuda_runtime.h>
#include <cuda_bf16.h>
#include <cstdint>

#define B_    128
#define S_    512
#define D_    2048
#define N_    128
#define NN_   16384
#define KTILE 64
#define ABW   144    /* A (bf16) smem row stride bytes: 128 data + 16 pad */
#define BPAD  72     /* B (fp32) smem row stride floats: 64 data + 8 pad */
#define STG   4
#define ATB   (128 * ABW)

// ---------------- scratch (device globals; no allocation) ----------------
__device__ __align__(16) __nv_bfloat16 g_meanbf[B_ * D_];  // 0.5 MB
__device__ __align__(16) __nv_bfloat16 g_ctxbf[B_ * D_];   // 0.5 MB (bf16 ctx, gemm2 A)
__device__ __align__(16) float g_ctxp[2 * B_ * D_];        // 2 MB gemm1 split-K partials
__device__ __align__(16) float g_part[128 * NN_];          // 8 MB raw split-K partials
__device__ __align__(16) float g_raw [NN_];                // 64 KB

// ---------------- helpers ----------------
__device__ __forceinline__ void cp_async16(void* smem, const void* gmem) {
    uint32_t s = (uint32_t)__cvta_generic_to_shared(smem);
    asm volatile("cp.async.cg.shared.global [%0], [%1], 16;\n" :: "r"(s), "l"(gmem));
}
__device__ __forceinline__ uint32_t f2bf2(float lo, float hi) {
    uint32_t r;
    asm("cvt.rn.bf16x2.f32 %0, %1, %2;" : "=r"(r) : "f"(hi), "f"(lo));  // hi -> upper 16
    return r;
}
__device__ __forceinline__ void mma_bf16(float* c, const uint32_t* a, const uint32_t* b) {
    asm volatile(
        "mma.sync.aligned.m16n8k16.row.col.f32.bf16.bf16.f32 "
        "{%0,%1,%2,%3}, {%4,%5,%6,%7}, {%8,%9}, {%0,%1,%2,%3};"
        : "+f"(c[0]), "+f"(c[1]), "+f"(c[2]), "+f"(c[3])
        : "r"(a[0]), "r"(a[1]), "r"(a[2]), "r"(a[3]), "r"(b[0]), "r"(b[1]));
}

// ---------------- kernel 1: mean over sequence -> bf16 ----------------
__global__ void k_mean(const float4* __restrict__ x4, uint2* __restrict__ mbf) {
    int b  = blockIdx.x >> 3;
    int d4 = ((blockIdx.x & 7) << 6) + threadIdx.x;     // 0..511
    const float4* p = x4 + (size_t)b * (S_ * D_ / 4) + d4;
    float4 acc[8];
    #pragma unroll
    for (int u = 0; u < 8; u++) acc[u] = make_float4(0.f, 0.f, 0.f, 0.f);
    for (int s = 0; s < S_; s += 8) {
        #pragma unroll
        for (int u = 0; u < 8; u++) {
            float4 v = __ldcs(&p[(size_t)(s + u) * (D_ / 4)]);
            acc[u].x += v.x; acc[u].y += v.y; acc[u].z += v.z; acc[u].w += v.w;
        }
    }
    #pragma unroll
    for (int u = 0; u < 4; u++) {
        acc[u].x += acc[u+4].x; acc[u].y += acc[u+4].y;
        acc[u].z += acc[u+4].z; acc[u].w += acc[u+4].w;
    }
    acc[0].x += acc[2].x; acc[0].y += acc[2].y; acc[0].z += acc[2].z; acc[0].w += acc[2].w;
    acc[1].x += acc[3].x; acc[1].y += acc[3].y; acc[1].z += acc[3].z; acc[1].w += acc[3].w;
    const float inv = 1.f / (float)S_;
    float mx = (acc[0].x + acc[1].x) * inv;
    float my = (acc[0].y + acc[1].y) * inv;
    float mz = (acc[0].z + acc[1].z) * inv;
    float mw = (acc[0].w + acc[1].w) * inv;
    mbf[b * (D_ / 4) + d4] = make_uint2(f2bf2(mx, my), f2bf2(mz, mw));
}

// ---------------- cp.async 4-stage GEMM: A bf16-smem, B fp32-smem ----------------
// out[128, NFULL] = A[128,2048] @ Bm[NFULL,2048]^T; NT cols per block.
// 256 threads = 8 warps as 2(M: 64-row groups) x 4(N: NT/4 quarters).
// MODE 0: split-K x2 partials. grid = 2 * NFULL/NT. out[split][128][NFULL] raw acc.
// MODE 3: full-K + fused softmax/einsum/sigmoid epilogue (NT = 128).
template<int NT, int NFULL, int MODE>
__global__ void __launch_bounds__(256, 1)
k_gemm(const __nv_bfloat16* __restrict__ Abf, const float* __restrict__ Bm,
       const float* __restrict__ bias, float* __restrict__ out,
       const float* __restrict__ adj, const float* __restrict__ raw) {
    constexpr int BTB = NT * BPAD * 4;   // B tile bytes per stage
    constexpr int NJ  = NT / 32;         // n8 tiles per warp (NT/4 cols / 8)
    constexpr int NAC = 4;               // A cp.async per thread (128*8/256)
    constexpr int NBC = NT * 16 / 256;   // B cp.async per thread

    extern __shared__ __align__(16) char smch[];
    float* sm = (float*)smch;
    char* Ab = smch;                      // [STG][128][ABW]
    char* Bb = smch + STG * ATB;          // [STG][NT][BPAD*4]

    const int tid  = threadIdx.x;
    const int warp = tid >> 5, lane = tid & 31;
    const int wy   = warp >> 2, wx = warp & 3;
    const int row0 = wy * 64;
    const int wxn0 = wx * (NT / 4);
    const int r    = lane >> 2, c = lane & 3;

    int n0, k0g, nkt;
    float* op = out;
    if (MODE == 0) {
        const int nblk = NFULL / NT;
        int split = blockIdx.x / nblk;
        n0  = (blockIdx.x % nblk) * NT;
        k0g = split * (D_ / 2);
        nkt = (D_ / 2) / KTILE;           // 16
        op  = out + (size_t)split * 128 * NFULL;
    } else {
        n0 = blockIdx.x * NT; k0g = 0; nkt = D_ / KTILE;   // 32
    }

    float acc[4][NJ][4];
    #pragma unroll
    for (int m = 0; m < 4; m++)
        #pragma unroll
        for (int j = 0; j < NJ; j++)
            acc[m][j][0] = acc[m][j][1] = acc[m][j][2] = acc[m][j][3] = 0.f;

    auto issue = [&](int kt) {
        const int st = kt % STG;
        const int k0 = k0g + kt * KTILE;
        #pragma unroll
        for (int u = 0; u < NAC; u++) {               // A: 128 rows x 64 bf16 (8 x 16B)
            int i = tid + u * 256, rr = i >> 3, c8 = i & 7;
            cp_async16(Ab + st * ATB + rr * ABW + c8 * 16,
                       &Abf[(size_t)rr * D_ + k0 + c8 * 8]);
        }
        #pragma unroll
        for (int u = 0; u < NBC; u++) {               // B: NT rows x 64 fp32 (16 x 16B)
            int i = tid + u * 256, rr = i >> 4, c16 = i & 15;
            cp_async16(Bb + st * BTB + rr * (BPAD * 4) + c16 * 16,
                       &Bm[(size_t)(n0 + rr) * D_ + k0 + c16 * 4]);
        }
    };

    #pragma unroll
    for (int s = 0; s < STG - 1; s++) {
        issue(s);
        asm volatile("cp.async.commit_group;\n");
    }

    for (int kt = 0; kt < nkt; kt++) {
        const int st = kt % STG;
        asm volatile("cp.async.wait_group %0;\n" :: "n"(STG - 2));
        __syncthreads();
        if (kt + STG - 1 < nkt) issue(kt + STG - 1);
        asm volatile("cp.async.commit_group;\n");

        const char*  Ast = Ab + st * ATB;
        const float* Bst = (const float*)(Bb + st * BTB);
        #pragma unroll
        for (int h = 0; h < 4; h++) {
            const int cb = h * 32 + 4 * c;            // A byte offset of k = 16h + 2c
            const int kb = h * 16 + 2 * c;            // B float offset
            uint32_t a[4][4];
            #pragma unroll
            for (int m = 0; m < 4; m++) {
                const char* ap = Ast + (row0 + m * 16 + r) * ABW;
                a[m][0] = *(const uint32_t*)(ap + cb);
                a[m][1] = *(const uint32_t*)(ap + 8 * ABW + cb);
                a[m][2] = *(const uint32_t*)(ap + cb + 16);
                a[m][3] = *(const uint32_t*)(ap + 8 * ABW + cb + 16);
            }
            #pragma unroll
            for (int j = 0; j < NJ; j++) {
                const float* bp = Bst + (wxn0 + j * 8 + r) * BPAD + kb;
                float2 v;
                uint32_t b[2];
                v = *(const float2*)(bp);       b[0] = f2bf2(v.x, v.y);
                v = *(const float2*)(bp + 8);   b[1] = f2bf2(v.x, v.y);
                #pragma unroll
                for (int m = 0; m < 4; m++) mma_bf16(acc[m][j], a[m], b);
            }
        }
        __syncthreads();
    }

    if (MODE == 0) {
        #pragma unroll
        for (int m = 0; m < 4; m++)
            #pragma unroll
            for (int j = 0; j < NJ; j++) {
                int row = row0 + m * 16 + r;
                int col = n0 + wxn0 + j * 8 + 2 * c;
                *(float2*)&op[(size_t)row * NFULL + col] =
                    make_float2(acc[m][j][0], acc[m][j][1]);
                *(float2*)&op[(size_t)(row + 8) * NFULL + col] =
                    make_float2(acc[m][j][2], acc[m][j][3]);
            }
    } else {
        // fused: logits = adj[i,:] + 0.1*(acc + bw); softmax over j; dot raw; sigmoid
        asm volatile("cp.async.wait_group 0;\n");
        __syncthreads();
        float* logit = sm;                 // [128][130]
        float* rawS  = sm + 128 * 130;     // [128][129]
        const float* adjr = adj + (size_t)blockIdx.x * 128;
        #pragma unroll
        for (int m = 0; m < 4; m++)
            #pragma unroll
            for (int j = 0; j < NJ; j++) {
                int row  = row0 + m * 16 + r;
                int lcol = wxn0 + j * 8 + 2 * c;
                int gcol = n0 + lcol;
                float b0 = bias[gcol], b1 = bias[gcol + 1];
                float a0 = adjr[lcol], a1 = adjr[lcol + 1];
                *(float2*)&logit[row * 130 + lcol] =
                    make_float2(a0 + 0.1f * (acc[m][j][0] + b0),
                                a1 + 0.1f * (acc[m][j][1] + b1));
                *(float2*)&logit[(row + 8) * 130 + lcol] =
                    make_float2(a0 + 0.1f * (acc[m][j][2] + b0),
                                a1 + 0.1f * (acc[m][j][3] + b1));
            }
        #pragma unroll
        for (int u = 0; u < 16; u++) {
            int i4 = tid + u * 256;                         // 0..4095
            float4 v = ((const float4*)raw)[i4];
            int b = i4 >> 5, j4 = (i4 & 31) * 4;
            float* d = &rawS[b * 129 + j4];
            d[0] = v.x; d[1] = v.y; d[2] = v.z; d[3] = v.w;
        }
        __syncthreads();
        if (tid < 128) {
            const float* L = &logit[tid * 130];
            const float* R = &rawS[tid * 129];
            float mx = -1e30f;
            #pragma unroll 4
            for (int j = 0; j < 128; j++) mx = fmaxf(mx, L[j]);
            float sum = 0.f, dot = 0.f;
            #pragma unroll 4
            for (int j = 0; j < 128; j++) {
                float e = __expf(L[j] - mx);
                sum += e;
                dot += e * R[j];
            }
            float w = dot / sum;
            out[(size_t)tid * N_ + blockIdx.x] = 1.f / (1.f + __expf(-w));
        }
    }
}

// ---------------- fused ctx-reduce + raw split-K partials ----------------
// grid 128 (K chunks of 16), block 256.
// cs = p0 + p1 + bc  (the ctx slice for this k-chunk); emits bf16 ctx for gemm2,
// then computes part[ks][b][j] = sum_{k in chunk} cs[b][k]*rs[j][k].
__global__ void k_rawctx(const float* __restrict__ ctxp, const float* __restrict__ bc,
                         const float* __restrict__ rs, float* __restrict__ part,
                         __nv_bfloat16* __restrict__ ctxbf) {
    __shared__ float cs [128][20];
    __shared__ float rss[128][20];
    const int tid = threadIdx.x;
    const int k0  = blockIdx.x * 16;
    const float* p0 = ctxp;
    const float* p1 = ctxp + (size_t)B_ * D_;
    #pragma unroll
    for (int u = 0; u < 2; u++) {
        int i  = tid + u * 256;
        int rr = i >> 2, cc = (i & 3) * 4;
        float4 a  = *(const float4*)&p0[(size_t)rr * D_ + k0 + cc];
        float4 b  = *(const float4*)&p1[(size_t)rr * D_ + k0 + cc];
        float4 bv = *(const float4*)&bc[k0 + cc];
        float4 s;
        s.x = a.x + b.x + bv.x; s.y = a.y + b.y + bv.y;
        s.z = a.z + b.z + bv.z; s.w = a.w + b.w + bv.w;
        *(float4*)&cs[rr][cc] = s;
        *(uint2*)&ctxbf[(size_t)rr * D_ + k0 + cc] =
            make_uint2(f2bf2(s.x, s.y), f2bf2(s.z, s.w));
        *(float4*)&rss[rr][cc] = *(const float4*)&rs[(size_t)rr * D_ + k0 + cc];
    }
    __syncthreads();
    const int bb = tid >> 4;
    const int jj = tid & 15;
    float a[8][8];
    #pragma unroll
    for (int u = 0; u < 8; u++)
        #pragma unroll
        for (int v = 0; v < 8; v++) a[u][v] = 0.f;
    #pragma unroll
    for (int k = 0; k < 16; k++) {
        float cv[8], rv[8];
        #pragma unroll
        for (int u = 0; u < 8; u++) { cv[u] = cs[bb + 16*u][k]; rv[u] = rss[jj + 16*u][k]; }
        #pragma unroll
        for (int u = 0; u < 8; u++)
            #pragma unroll
            for (int v = 0; v < 8; v++) a[u][v] += cv[u] * rv[v];
    }
    float* po = part + (size_t)blockIdx.x * NN_;
    #pragma unroll
    for (int u = 0; u < 8; u++)
        #pragma unroll
        for (int v = 0; v < 8; v++)
            po[(bb + 16*u) * N_ + (jj + 16*v)] = a[u][v];
}

// ---------------- raw reduce over 128 partials ----------------
__global__ void k_rawred(const float* __restrict__ part, float* __restrict__ raw) {
    int i = blockIdx.x * 256 + threadIdx.x;   // 0..16383
    float s = 0.f;
    #pragma unroll 8
    for (int ks = 0; ks < 128; ks++) s += part[(size_t)ks * NN_ + i];
    raw[i] = s;
}

// ---------------- launch ----------------
extern "C" void kernel_launch(void* const* d_in, const int* in_sizes, int n_in,
                              void* d_out, int out_size) {
    const float* x   = (const float*)d_in[0];
    const float* rs  = (const float*)d_in[1];
    const float* Wc  = (const float*)d_in[2];
    const float* bc  = (const float*)d_in[3];
    const float* Ww  = (const float*)d_in[4];
    const float* bw  = (const float*)d_in[5];
    const float* adj = (const float*)d_in[6];
    float* out = (float*)d_out;

    __nv_bfloat16 *p_meanbf, *p_ctxbf;
    float *p_ctxp, *p_part, *p_raw;
    cudaGetSymbolAddress((void**)&p_meanbf, g_meanbf);
    cudaGetSymbolAddress((void**)&p_ctxbf, g_ctxbf);
    cudaGetSymbolAddress((void**)&p_ctxp,  g_ctxp);
    cudaGetSymbolAddress((void**)&p_part,  g_part);
    cudaGetSymbolAddress((void**)&p_raw,   g_raw);

    // 1. mean over S (HBM-bound, 512 MB) -> bf16
    k_mean<<<B_ * 8, 64>>>((const float4*)x, (uint2*)p_meanbf);

    // 2. context partials: split-K x2, 128 blocks
    {
        size_t sh = (size_t)STG * (ATB + 32 * BPAD * 4);               // 4*(18432+9216)
        cudaFuncSetAttribute((const void*)k_gemm<32, D_, 0>,
                             cudaFuncAttributeMaxDynamicSharedMemorySize, (int)sh);
        k_gemm<32, D_, 0><<<128, 256, sh>>>(p_meanbf, Wc, nullptr, p_ctxp, nullptr, nullptr);
    }

    // 3. fused: ctx = p0+p1+bc (-> bf16) + raw split-K partials; then reduce
    k_rawctx<<<128, 256>>>(p_ctxp, bc, rs, p_part, p_ctxbf);
    k_rawred<<<64, 256>>>(p_part, p_raw);

    // 4+5. warp GEMM + fused softmax/einsum/sigmoid
    {
        size_t stages = (size_t)STG * (ATB + 128 * BPAD * 4);          // 221,184 B
        size_t epi    = (size_t)(128 * 130 + 128 * 129) * 4;           // 132,608 B
        size_t sh     = stages > epi ? stages : epi;
        cudaFuncSetAttribute((const void*)k_gemm<128, NN_, 3>,
                             cudaFuncAttributeMaxDynamicSharedMemorySize, (int)sh);
        k_gemm<128, NN_, 3><<<128, 256, sh>>>(p_ctxbf, Ww, bw, out, adj, p_raw);
    }
}

// round 11
// speedup vs baseline: 1.2499x; 1.0143x over previous
#include <cuda_runtime.h>
#include <cuda_bf16.h>
#include <cstdint>

#define B_    128
#define S_    512
#define D_    2048
#define N_    128
#define NN_   16384
#define KTILE 64
#define ABW   144    /* A (bf16) smem row stride bytes: 128 data + 16 pad */
#define BPAD  72     /* B (fp32) smem row stride floats: 64 data + 8 pad */
#define STG   4
#define ATB   (128 * ABW)

// ---------------- scratch (device globals; no allocation) ----------------
__device__ __align__(16) __nv_bfloat16 g_meanbf[B_ * D_];  // 0.5 MB
__device__ __align__(16) __nv_bfloat16 g_ctxbf[B_ * D_];   // 0.5 MB (bf16 ctx, gemm2 A)
__device__ __align__(16) float g_ctxp[2 * B_ * D_];        // 2 MB gemm1 split-K partials
__device__ __align__(16) float g_part[128 * NN_];          // 8 MB raw split-K partials
__device__ __align__(16) float g_raw [NN_];                // 64 KB

// ---------------- helpers ----------------
__device__ __forceinline__ void cp_async16(void* smem, const void* gmem) {
    uint32_t s = (uint32_t)__cvta_generic_to_shared(smem);
    asm volatile("cp.async.cg.shared.global [%0], [%1], 16;\n" :: "r"(s), "l"(gmem));
}
__device__ __forceinline__ uint32_t f2bf2(float lo, float hi) {
    uint32_t r;
    asm("cvt.rn.bf16x2.f32 %0, %1, %2;" : "=r"(r) : "f"(hi), "f"(lo));  // hi -> upper 16
    return r;
}
__device__ __forceinline__ void mma_bf16(float* c, const uint32_t* a, const uint32_t* b) {
    asm volatile(
        "mma.sync.aligned.m16n8k16.row.col.f32.bf16.bf16.f32 "
        "{%0,%1,%2,%3}, {%4,%5,%6,%7}, {%8,%9}, {%0,%1,%2,%3};"
        : "+f"(c[0]), "+f"(c[1]), "+f"(c[2]), "+f"(c[3])
        : "r"(a[0]), "r"(a[1]), "r"(a[2]), "r"(a[3]), "r"(b[0]), "r"(b[1]));
}

// ---------------- kernel 1: mean over sequence -> bf16 ----------------
__global__ void k_mean(const float4* __restrict__ x4, uint2* __restrict__ mbf) {
    int b  = blockIdx.x >> 3;
    int d4 = ((blockIdx.x & 7) << 6) + threadIdx.x;     // 0..511
    const float4* p = x4 + (size_t)b * (S_ * D_ / 4) + d4;
    float4 acc[8];
    #pragma unroll
    for (int u = 0; u < 8; u++) acc[u] = make_float4(0.f, 0.f, 0.f, 0.f);
    for (int s = 0; s < S_; s += 8) {
        #pragma unroll
        for (int u = 0; u < 8; u++) {
            float4 v = __ldcs(&p[(size_t)(s + u) * (D_ / 4)]);
            acc[u].x += v.x; acc[u].y += v.y; acc[u].z += v.z; acc[u].w += v.w;
        }
    }
    #pragma unroll
    for (int u = 0; u < 4; u++) {
        acc[u].x += acc[u+4].x; acc[u].y += acc[u+4].y;
        acc[u].z += acc[u+4].z; acc[u].w += acc[u+4].w;
    }
    acc[0].x += acc[2].x; acc[0].y += acc[2].y; acc[0].z += acc[2].z; acc[0].w += acc[2].w;
    acc[1].x += acc[3].x; acc[1].y += acc[3].y; acc[1].z += acc[3].z; acc[1].w += acc[3].w;
    const float inv = 1.f / (float)S_;
    float mx = (acc[0].x + acc[1].x) * inv;
    float my = (acc[0].y + acc[1].y) * inv;
    float mz = (acc[0].z + acc[1].z) * inv;
    float mw = (acc[0].w + acc[1].w) * inv;
    mbf[b * (D_ / 4) + d4] = make_uint2(f2bf2(mx, my), f2bf2(mz, mw));
}

// ---------------- cp.async 4-stage GEMM: A bf16-smem, B fp32-smem ----------------
// out[128, NFULL] = A[128,2048] @ Bm[NFULL,2048]^T; NT cols per block.
// 256 threads = 8 warps as 2(M: 64-row groups) x 4(N: NT/4 quarters).
// MODE 0: split-K x2 partials. grid = 2 * NFULL/NT. out[split][128][NFULL] raw acc.
// MODE 3: full-K + fused softmax/einsum/sigmoid epilogue (NT = 128).
template<int NT, int NFULL, int MODE>
__global__ void __launch_bounds__(256, 1)
k_gemm(const __nv_bfloat16* __restrict__ Abf, const float* __restrict__ Bm,
       const float* __restrict__ bias, float* __restrict__ out,
       const float* __restrict__ adj, const float* __restrict__ raw) {
    constexpr int BTB = NT * BPAD * 4;   // B tile bytes per stage
    constexpr int NJ  = NT / 32;         // n8 tiles per warp (NT/4 cols / 8)
    constexpr int NAC = 4;               // A cp.async per thread (128*8/256)
    constexpr int NBC = NT * 16 / 256;   // B cp.async per thread

    extern __shared__ __align__(16) char smch[];
    float* sm = (float*)smch;
    char* Ab = smch;                      // [STG][128][ABW]
    char* Bb = smch + STG * ATB;          // [STG][NT][BPAD*4]

    const int tid  = threadIdx.x;
    const int warp = tid >> 5, lane = tid & 31;
    const int wy   = warp >> 2, wx = warp & 3;
    const int row0 = wy * 64;
    const int wxn0 = wx * (NT / 4);
    const int r    = lane >> 2, c = lane & 3;

    int n0, k0g, nkt;
    float* op = out;
    if (MODE == 0) {
        const int nblk = NFULL / NT;
        int split = blockIdx.x / nblk;
        n0  = (blockIdx.x % nblk) * NT;
        k0g = split * (D_ / 2);
        nkt = (D_ / 2) / KTILE;           // 16
        op  = out + (size_t)split * 128 * NFULL;
    } else {
        n0 = blockIdx.x * NT; k0g = 0; nkt = D_ / KTILE;   // 32
    }

    float acc[4][NJ][4];
    #pragma unroll
    for (int m = 0; m < 4; m++)
        #pragma unroll
        for (int j = 0; j < NJ; j++)
            acc[m][j][0] = acc[m][j][1] = acc[m][j][2] = acc[m][j][3] = 0.f;

    auto issue = [&](int kt) {
        const int st = kt % STG;
        const int k0 = k0g + kt * KTILE;
        #pragma unroll
        for (int u = 0; u < NAC; u++) {               // A: 128 rows x 64 bf16 (8 x 16B)
            int i = tid + u * 256, rr = i >> 3, c8 = i & 7;
            cp_async16(Ab + st * ATB + rr * ABW + c8 * 16,
                       &Abf[(size_t)rr * D_ + k0 + c8 * 8]);
        }
        #pragma unroll
        for (int u = 0; u < NBC; u++) {               // B: NT rows x 64 fp32 (16 x 16B)
            int i = tid + u * 256, rr = i >> 4, c16 = i & 15;
            cp_async16(Bb + st * BTB + rr * (BPAD * 4) + c16 * 16,
                       &Bm[(size_t)(n0 + rr) * D_ + k0 + c16 * 4]);
        }
    };

    #pragma unroll
    for (int s = 0; s < STG - 1; s++) {
        issue(s);
        asm volatile("cp.async.commit_group;\n");
    }

    for (int kt = 0; kt < nkt; kt++) {
        const int st = kt % STG;
        asm volatile("cp.async.wait_group %0;\n" :: "n"(STG - 2));
        __syncthreads();
        if (kt + STG - 1 < nkt) issue(kt + STG - 1);
        asm volatile("cp.async.commit_group;\n");

        const char*  Ast = Ab + st * ATB;
        const float* Bst = (const float*)(Bb + st * BTB);
        #pragma unroll
        for (int h = 0; h < 4; h++) {
            const int cb = h * 32 + 4 * c;            // A byte offset of k = 16h + 2c
            const int kb = h * 16 + 2 * c;            // B float offset
            uint32_t a[4][4];
            #pragma unroll
            for (int m = 0; m < 4; m++) {
                const char* ap = Ast + (row0 + m * 16 + r) * ABW;
                a[m][0] = *(const uint32_t*)(ap + cb);
                a[m][1] = *(const uint32_t*)(ap + 8 * ABW + cb);
                a[m][2] = *(const uint32_t*)(ap + cb + 16);
                a[m][3] = *(const uint32_t*)(ap + 8 * ABW + cb + 16);
            }
            #pragma unroll
            for (int j = 0; j < NJ; j++) {
                const float* bp = Bst + (wxn0 + j * 8 + r) * BPAD + kb;
                float2 v;
                uint32_t b[2];
                v = *(const float2*)(bp);       b[0] = f2bf2(v.x, v.y);
                v = *(const float2*)(bp + 8);   b[1] = f2bf2(v.x, v.y);
                #pragma unroll
                for (int m = 0; m < 4; m++) mma_bf16(acc[m][j], a[m], b);
            }
        }
        __syncthreads();
    }

    if (MODE == 0) {
        #pragma unroll
        for (int m = 0; m < 4; m++)
            #pragma unroll
            for (int j = 0; j < NJ; j++) {
                int row = row0 + m * 16 + r;
                int col = n0 + wxn0 + j * 8 + 2 * c;
                *(float2*)&op[(size_t)row * NFULL + col] =
                    make_float2(acc[m][j][0], acc[m][j][1]);
                *(float2*)&op[(size_t)(row + 8) * NFULL + col] =
                    make_float2(acc[m][j][2], acc[m][j][3]);
            }
    } else {
        // fused: logits = adj[i,:] + 0.1*(acc + bw); softmax over j; dot raw; sigmoid
        asm volatile("cp.async.wait_group 0;\n");
        __syncthreads();
        float* logit = sm;                 // [128][130]
        float* rawS  = sm + 128 * 130;     // [128][129]
        const float* adjr = adj + (size_t)blockIdx.x * 128;
        #pragma unroll
        for (int m = 0; m < 4; m++)
            #pragma unroll
            for (int j = 0; j < NJ; j++) {
                int row  = row0 + m * 16 + r;
                int lcol = wxn0 + j * 8 + 2 * c;
                int gcol = n0 + lcol;
                float b0 = bias[gcol], b1 = bias[gcol + 1];
                float a0 = adjr[lcol], a1 = adjr[lcol + 1];
                *(float2*)&logit[row * 130 + lcol] =
                    make_float2(a0 + 0.1f * (acc[m][j][0] + b0),
                                a1 + 0.1f * (acc[m][j][1] + b1));
                *(float2*)&logit[(row + 8) * 130 + lcol] =
                    make_float2(a0 + 0.1f * (acc[m][j][2] + b0),
                                a1 + 0.1f * (acc[m][j][3] + b1));
            }
        #pragma unroll
        for (int u = 0; u < 16; u++) {
            int i4 = tid + u * 256;                         // 0..4095
            float4 v = ((const float4*)raw)[i4];
            int b = i4 >> 5, j4 = (i4 & 31) * 4;
            float* d = &rawS[b * 129 + j4];
            d[0] = v.x; d[1] = v.y; d[2] = v.z; d[3] = v.w;
        }
        __syncthreads();
        if (tid < 128) {
            const float* L = &logit[tid * 130];
            const float* R = &rawS[tid * 129];
            float mx = -1e30f;
            #pragma unroll 4
            for (int j = 0; j < 128; j++) mx = fmaxf(mx, L[j]);
            float sum = 0.f, dot = 0.f;
            #pragma unroll 4
            for (int j = 0; j < 128; j++) {
                float e = __expf(L[j] - mx);
                sum += e;
                dot += e * R[j];
            }
            float w = dot / sum;
            out[(size_t)tid * N_ + blockIdx.x] = 1.f / (1.f + __expf(-w));
        }
    }
}

// ---------------- fused ctx-reduce + raw split-K partials ----------------
// grid 128 (K chunks of 16), block 256.
// cs = p0 + p1 + bc  (the ctx slice for this k-chunk); emits bf16 ctx for gemm2,
// then computes part[ks][b][j] = sum_{k in chunk} cs[b][k]*rs[j][k].
__global__ void k_rawctx(const float* __restrict__ ctxp, const float* __restrict__ bc,
                         const float* __restrict__ rs, float* __restrict__ part,
                         __nv_bfloat16* __restrict__ ctxbf) {
    __shared__ float cs [128][20];
    __shared__ float rss[128][20];
    const int tid = threadIdx.x;
    const int k0  = blockIdx.x * 16;
    const float* p0 = ctxp;
    const float* p1 = ctxp + (size_t)B_ * D_;
    #pragma unroll
    for (int u = 0; u < 2; u++) {
        int i  = tid + u * 256;
        int rr = i >> 2, cc = (i & 3) * 4;
        float4 a  = *(const float4*)&p0[(size_t)rr * D_ + k0 + cc];
        float4 b  = *(const float4*)&p1[(size_t)rr * D_ + k0 + cc];
        float4 bv = *(const float4*)&bc[k0 + cc];
        float4 s;
        s.x = a.x + b.x + bv.x; s.y = a.y + b.y + bv.y;
        s.z = a.z + b.z + bv.z; s.w = a.w + b.w + bv.w;
        *(float4*)&cs[rr][cc] = s;
        *(uint2*)&ctxbf[(size_t)rr * D_ + k0 + cc] =
            make_uint2(f2bf2(s.x, s.y), f2bf2(s.z, s.w));
        *(float4*)&rss[rr][cc] = *(const float4*)&rs[(size_t)rr * D_ + k0 + cc];
    }
    __syncthreads();
    const int bb = tid >> 4;
    const int jj = tid & 15;
    float a[8][8];
    #pragma unroll
    for (int u = 0; u < 8; u++)
        #pragma unroll
        for (int v = 0; v < 8; v++) a[u][v] = 0.f;
    #pragma unroll
    for (int k = 0; k < 16; k++) {
        float cv[8], rv[8];
        #pragma unroll
        for (int u = 0; u < 8; u++) { cv[u] = cs[bb + 16*u][k]; rv[u] = rss[jj + 16*u][k]; }
        #pragma unroll
        for (int u = 0; u < 8; u++)
            #pragma unroll
            for (int v = 0; v < 8; v++) a[u][v] += cv[u] * rv[v];
    }
    float* po = part + (size_t)blockIdx.x * NN_;
    #pragma unroll
    for (int u = 0; u < 8; u++)
        #pragma unroll
        for (int v = 0; v < 8; v++)
            po[(bb + 16*u) * N_ + (jj + 16*v)] = a[u][v];
}

// ---------------- raw reduce over 128 partials: 256 blocks, 4-way ks split ----------------
__global__ void k_rawred(const float* __restrict__ part, float* __restrict__ raw) {
    __shared__ float red[4][64];
    const int o  = (blockIdx.x << 6) + (threadIdx.x & 63);   // output index
    const int g  = threadIdx.x >> 6;                          // ks group 0..3
    float s = 0.f;
    #pragma unroll 8
    for (int ks = g * 32; ks < g * 32 + 32; ks++)
        s += part[(size_t)ks * NN_ + o];
    red[g][threadIdx.x & 63] = s;
    __syncthreads();
    if (threadIdx.x < 64)
        raw[(blockIdx.x << 6) + threadIdx.x] =
            (red[0][threadIdx.x] + red[1][threadIdx.x]) +
            (red[2][threadIdx.x] + red[3][threadIdx.x]);
}

// ---------------- launch ----------------
extern "C" void kernel_launch(void* const* d_in, const int* in_sizes, int n_in,
                              void* d_out, int out_size) {
    const float* x   = (const float*)d_in[0];
    const float* rs  = (const float*)d_in[1];
    const float* Wc  = (const float*)d_in[2];
    const float* bc  = (const float*)d_in[3];
    const float* Ww  = (const float*)d_in[4];
    const float* bw  = (const float*)d_in[5];
    const float* adj = (const float*)d_in[6];
    float* out = (float*)d_out;

    __nv_bfloat16 *p_meanbf, *p_ctxbf;
    float *p_ctxp, *p_part, *p_raw;
    cudaGetSymbolAddress((void**)&p_meanbf, g_meanbf);
    cudaGetSymbolAddress((void**)&p_ctxbf, g_ctxbf);
    cudaGetSymbolAddress((void**)&p_ctxp,  g_ctxp);
    cudaGetSymbolAddress((void**)&p_part,  g_part);
    cudaGetSymbolAddress((void**)&p_raw,   g_raw);

    // 1. mean over S (HBM-bound, 512 MB) -> bf16
    k_mean<<<B_ * 8, 64>>>((const float4*)x, (uint2*)p_meanbf);

    // 2. context partials: split-K x2, 128 blocks
    {
        size_t sh = (size_t)STG * (ATB + 32 * BPAD * 4);               // 4*(18432+9216)
        cudaFuncSetAttribute((const void*)k_gemm<32, D_, 0>,
                             cudaFuncAttributeMaxDynamicSharedMemorySize, (int)sh);
        k_gemm<32, D_, 0><<<128, 256, sh>>>(p_meanbf, Wc, nullptr, p_ctxp, nullptr, nullptr);
    }

    // 3. fused: ctx = p0+p1+bc (-> bf16) + raw split-K partials; then reduce
    k_rawctx<<<128, 256>>>(p_ctxp, bc, rs, p_part, p_ctxbf);
    k_rawred<<<256, 256>>>(p_part, p_raw);

    // 4+5. warp GEMM + fused softmax/einsum/sigmoid
    {
        size_t stages = (size_t)STG * (ATB + 128 * BPAD * 4);          // 221,184 B
        size_t epi    = (size_t)(128 * 130 + 128 * 129) * 4;           // 132,608 B
        size_t sh     = stages > epi ? stages : epi;
        cudaFuncSetAttribute((const void*)k_gemm<128, NN_, 3>,
                             cudaFuncAttributeMaxDynamicSharedMemorySize, (int)sh);
        k_gemm<128, NN_, 3><<<128, 256, sh>>>(p_ctxbf, Ww, bw, out, adj, p_raw);
    }
}

// round 12
// speedup vs baseline: 1.2533x; 1.0027x over previous
#include <cuda_runtime.h>
#include <cuda_bf16.h>
#include <cstdint>

#define B_    128
#define S_    512
#define D_    2048
#define N_    128
#define NN_   16384
#define KTILE 64
#define ABW   144    /* A (bf16) smem row stride bytes: 128 data + 16 pad */
#define BPAD  72     /* B (fp32) smem row stride floats: 64 data + 8 pad */
#define STG   4
#define ATB   (128 * ABW)

// ---------------- scratch (device globals; no allocation) ----------------
__device__ __align__(16) __nv_bfloat16 g_meanbf[B_ * D_];  // 0.5 MB
__device__ __align__(16) __nv_bfloat16 g_ctxbf[B_ * D_];   // 0.5 MB (bf16 ctx, gemm2 A)
__device__ __align__(16) float g_ctxp[2 * B_ * D_];        // 2 MB gemm1 split-K partials
__device__ __align__(16) float g_part[128 * NN_];          // 8 MB raw split-K partials
__device__ __align__(16) float g_raw [NN_];                // 64 KB

// ---------------- helpers ----------------
__device__ __forceinline__ void cp_async16(void* smem, const void* gmem) {
    uint32_t s = (uint32_t)__cvta_generic_to_shared(smem);
    asm volatile("cp.async.cg.shared.global [%0], [%1], 16;\n" :: "r"(s), "l"(gmem));
}
__device__ __forceinline__ uint32_t f2bf2(float lo, float hi) {
    uint32_t r;
    asm("cvt.rn.bf16x2.f32 %0, %1, %2;" : "=r"(r) : "f"(hi), "f"(lo));  // hi -> upper 16
    return r;
}
__device__ __forceinline__ void mma_bf16(float* c, const uint32_t* a, const uint32_t* b) {
    asm volatile(
        "mma.sync.aligned.m16n8k16.row.col.f32.bf16.bf16.f32 "
        "{%0,%1,%2,%3}, {%4,%5,%6,%7}, {%8,%9}, {%0,%1,%2,%3};"
        : "+f"(c[0]), "+f"(c[1]), "+f"(c[2]), "+f"(c[3])
        : "r"(a[0]), "r"(a[1]), "r"(a[2]), "r"(a[3]), "r"(b[0]), "r"(b[1]));
}

// ---------------- kernel 1: mean over sequence -> bf16 ----------------
__global__ void k_mean(const float4* __restrict__ x4, uint2* __restrict__ mbf) {
    int b  = blockIdx.x >> 3;
    int d4 = ((blockIdx.x & 7) << 6) + threadIdx.x;     // 0..511
    const float4* p = x4 + (size_t)b * (S_ * D_ / 4) + d4;
    float4 acc[8];
    #pragma unroll
    for (int u = 0; u < 8; u++) acc[u] = make_float4(0.f, 0.f, 0.f, 0.f);
    for (int s = 0; s < S_; s += 8) {
        #pragma unroll
        for (int u = 0; u < 8; u++) {
            float4 v = __ldcs(&p[(size_t)(s + u) * (D_ / 4)]);
            acc[u].x += v.x; acc[u].y += v.y; acc[u].z += v.z; acc[u].w += v.w;
        }
    }
    #pragma unroll
    for (int u = 0; u < 4; u++) {
        acc[u].x += acc[u+4].x; acc[u].y += acc[u+4].y;
        acc[u].z += acc[u+4].z; acc[u].w += acc[u+4].w;
    }
    acc[0].x += acc[2].x; acc[0].y += acc[2].y; acc[0].z += acc[2].z; acc[0].w += acc[2].w;
    acc[1].x += acc[3].x; acc[1].y += acc[3].y; acc[1].z += acc[3].z; acc[1].w += acc[3].w;
    const float inv = 1.f / (float)S_;
    float mx = (acc[0].x + acc[1].x) * inv;
    float my = (acc[0].y + acc[1].y) * inv;
    float mz = (acc[0].z + acc[1].z) * inv;
    float mw = (acc[0].w + acc[1].w) * inv;
    mbf[b * (D_ / 4) + d4] = make_uint2(f2bf2(mx, my), f2bf2(mz, mw));
}

// ---------------- cp.async 4-stage GEMM: A bf16-smem, B fp32-smem ----------------
// out[128, NFULL] = A[128,2048] @ Bm[NFULL,2048]^T; NT cols per block.
// 256 threads = 8 warps laid out WY(M) x WX(N). Single sync per ktile.
// MODE 0: split-K x2 partials. grid = 2 * NFULL/NT. out[split][128][NFULL] raw acc.
// MODE 3: full-K + fused softmax/einsum/sigmoid epilogue (NT = 128).
template<int NT, int NFULL, int MODE, int WY, int WX>
__global__ void __launch_bounds__(256, 1)
k_gemm(const __nv_bfloat16* __restrict__ Abf, const float* __restrict__ Bm,
       const float* __restrict__ bias, float* __restrict__ out,
       const float* __restrict__ adj, const float* __restrict__ raw) {
    constexpr int BTB = NT * BPAD * 4;   // B tile bytes per stage
    constexpr int MW  = 128 / WY / 16;   // m16 tiles per warp
    constexpr int NJ  = NT / WX / 8;     // n8 tiles per warp
    constexpr int NAC = 4;               // A cp.async per thread (128*8/256)
    constexpr int NBC = NT * 16 / 256;   // B cp.async per thread

    extern __shared__ __align__(16) char smch[];
    float* sm = (float*)smch;
    char* Ab = smch;                      // [STG][128][ABW]
    char* Bb = smch + STG * ATB;          // [STG][NT][BPAD*4]

    const int tid  = threadIdx.x;
    const int warp = tid >> 5, lane = tid & 31;
    const int wy   = warp / WX, wx = warp % WX;
    const int row0 = wy * (128 / WY);
    const int wxn0 = wx * (NT / WX);
    const int r    = lane >> 2, c = lane & 3;

    int n0, k0g, nkt;
    float* op = out;
    if (MODE == 0) {
        const int nblk = NFULL / NT;
        int split = blockIdx.x / nblk;
        n0  = (blockIdx.x % nblk) * NT;
        k0g = split * (D_ / 2);
        nkt = (D_ / 2) / KTILE;           // 16
        op  = out + (size_t)split * 128 * NFULL;
    } else {
        n0 = blockIdx.x * NT; k0g = 0; nkt = D_ / KTILE;   // 32
    }

    float acc[MW][NJ][4];
    #pragma unroll
    for (int m = 0; m < MW; m++)
        #pragma unroll
        for (int j = 0; j < NJ; j++)
            acc[m][j][0] = acc[m][j][1] = acc[m][j][2] = acc[m][j][3] = 0.f;

    auto issue = [&](int kt) {
        const int st = kt % STG;
        const int k0 = k0g + kt * KTILE;
        #pragma unroll
        for (int u = 0; u < NAC; u++) {               // A: 128 rows x 64 bf16 (8 x 16B)
            int i = tid + u * 256, rr = i >> 3, c8 = i & 7;
            cp_async16(Ab + st * ATB + rr * ABW + c8 * 16,
                       &Abf[(size_t)rr * D_ + k0 + c8 * 8]);
        }
        #pragma unroll
        for (int u = 0; u < NBC; u++) {               // B: NT rows x 64 fp32 (16 x 16B)
            int i = tid + u * 256, rr = i >> 4, c16 = i & 15;
            cp_async16(Bb + st * BTB + rr * (BPAD * 4) + c16 * 16,
                       &Bm[(size_t)(n0 + rr) * D_ + k0 + c16 * 4]);
        }
    };

    #pragma unroll
    for (int s = 0; s < STG - 1; s++) {
        issue(s);
        asm volatile("cp.async.commit_group;\n");
    }

    for (int kt = 0; kt < nkt; kt++) {
        const int st = kt % STG;
        asm volatile("cp.async.wait_group %0;\n" :: "n"(STG - 2));
        __syncthreads();
        // issue(kt+3) overwrites stage (kt-1)%4; its tile was consumed at iter kt-1,
        // and every thread passed that compute before this iteration's sync. Safe.
        if (kt + STG - 1 < nkt) issue(kt + STG - 1);
        asm volatile("cp.async.commit_group;\n");

        const char*  Ast = Ab + st * ATB;
        const float* Bst = (const float*)(Bb + st * BTB);
        #pragma unroll
        for (int h = 0; h < 4; h++) {
            const int cb = h * 32 + 4 * c;            // A byte offset of k = 16h + 2c
            const int kb = h * 16 + 2 * c;            // B float offset
            uint32_t a[MW][4];
            #pragma unroll
            for (int m = 0; m < MW; m++) {
                const char* ap = Ast + (row0 + m * 16 + r) * ABW;
                a[m][0] = *(const uint32_t*)(ap + cb);
                a[m][1] = *(const uint32_t*)(ap + 8 * ABW + cb);
                a[m][2] = *(const uint32_t*)(ap + cb + 16);
                a[m][3] = *(const uint32_t*)(ap + 8 * ABW + cb + 16);
            }
            #pragma unroll
            for (int j = 0; j < NJ; j++) {
                const float* bp = Bst + (wxn0 + j * 8 + r) * BPAD + kb;
                float2 v;
                uint32_t b[2];
                v = *(const float2*)(bp);       b[0] = f2bf2(v.x, v.y);
                v = *(const float2*)(bp + 8);   b[1] = f2bf2(v.x, v.y);
                #pragma unroll
                for (int m = 0; m < MW; m++) mma_bf16(acc[m][j], a[m], b);
            }
        }
    }

    if (MODE == 0) {
        #pragma unroll
        for (int m = 0; m < MW; m++)
            #pragma unroll
            for (int j = 0; j < NJ; j++) {
                int row = row0 + m * 16 + r;
                int col = n0 + wxn0 + j * 8 + 2 * c;
                *(float2*)&op[(size_t)row * NFULL + col] =
                    make_float2(acc[m][j][0], acc[m][j][1]);
                *(float2*)&op[(size_t)(row + 8) * NFULL + col] =
                    make_float2(acc[m][j][2], acc[m][j][3]);
            }
    } else {
        // fused: logits = adj[i,:] + 0.1*(acc + bw); softmax over j; dot raw; sigmoid
        asm volatile("cp.async.wait_group 0;\n");
        __syncthreads();
        float* logit = sm;                 // [128][130]
        float* rawS  = sm + 128 * 130;     // [128][129]
        const float* adjr = adj + (size_t)blockIdx.x * 128;
        #pragma unroll
        for (int m = 0; m < MW; m++)
            #pragma unroll
            for (int j = 0; j < NJ; j++) {
                int row  = row0 + m * 16 + r;
                int lcol = wxn0 + j * 8 + 2 * c;
                int gcol = n0 + lcol;
                float b0 = bias[gcol], b1 = bias[gcol + 1];
                float a0 = adjr[lcol], a1 = adjr[lcol + 1];
                *(float2*)&logit[row * 130 + lcol] =
                    make_float2(a0 + 0.1f * (acc[m][j][0] + b0),
                                a1 + 0.1f * (acc[m][j][1] + b1));
                *(float2*)&logit[(row + 8) * 130 + lcol] =
                    make_float2(a0 + 0.1f * (acc[m][j][2] + b0),
                                a1 + 0.1f * (acc[m][j][3] + b1));
            }
        #pragma unroll
        for (int u = 0; u < 16; u++) {
            int i4 = tid + u * 256;                         // 0..4095
            float4 v = ((const float4*)raw)[i4];
            int b = i4 >> 5, j4 = (i4 & 31) * 4;
            float* d = &rawS[b * 129 + j4];
            d[0] = v.x; d[1] = v.y; d[2] = v.z; d[3] = v.w;
        }
        __syncthreads();
        if (tid < 128) {
            const float* L = &logit[tid * 130];
            const float* R = &rawS[tid * 129];
            float mx = -1e30f;
            #pragma unroll 4
            for (int j = 0; j < 128; j++) mx = fmaxf(mx, L[j]);
            float sum = 0.f, dot = 0.f;
            #pragma unroll 4
            for (int j = 0; j < 128; j++) {
                float e = __expf(L[j] - mx);
                sum += e;
                dot += e * R[j];
            }
            float w = dot / sum;
            out[(size_t)tid * N_ + blockIdx.x] = 1.f / (1.f + __expf(-w));
        }
    }
}

// ---------------- fused ctx-reduce + raw split-K partials ----------------
// grid 128 (K chunks of 16), block 256.
__global__ void k_rawctx(const float* __restrict__ ctxp, const float* __restrict__ bc,
                         const float* __restrict__ rs, float* __restrict__ part,
                         __nv_bfloat16* __restrict__ ctxbf) {
    __shared__ float cs [128][20];
    __shared__ float rss[128][20];
    const int tid = threadIdx.x;
    const int k0  = blockIdx.x * 16;
    const float* p0 = ctxp;
    const float* p1 = ctxp + (size_t)B_ * D_;
    #pragma unroll
    for (int u = 0; u < 2; u++) {
        int i  = tid + u * 256;
        int rr = i >> 2, cc = (i & 3) * 4;
        float4 a  = *(const float4*)&p0[(size_t)rr * D_ + k0 + cc];
        float4 b  = *(const float4*)&p1[(size_t)rr * D_ + k0 + cc];
        float4 bv = *(const float4*)&bc[k0 + cc];
        float4 s;
        s.x = a.x + b.x + bv.x; s.y = a.y + b.y + bv.y;
        s.z = a.z + b.z + bv.z; s.w = a.w + b.w + bv.w;
        *(float4*)&cs[rr][cc] = s;
        *(uint2*)&ctxbf[(size_t)rr * D_ + k0 + cc] =
            make_uint2(f2bf2(s.x, s.y), f2bf2(s.z, s.w));
        *(float4*)&rss[rr][cc] = *(const float4*)&rs[(size_t)rr * D_ + k0 + cc];
    }
    __syncthreads();
    const int bb = tid >> 4;
    const int jj = tid & 15;
    float a[8][8];
    #pragma unroll
    for (int u = 0; u < 8; u++)
        #pragma unroll
        for (int v = 0; v < 8; v++) a[u][v] = 0.f;
    #pragma unroll
    for (int k = 0; k < 16; k++) {
        float cv[8], rv[8];
        #pragma unroll
        for (int u = 0; u < 8; u++) { cv[u] = cs[bb + 16*u][k]; rv[u] = rss[jj + 16*u][k]; }
        #pragma unroll
        for (int u = 0; u < 8; u++)
            #pragma unroll
            for (int v = 0; v < 8; v++) a[u][v] += cv[u] * rv[v];
    }
    float* po = part + (size_t)blockIdx.x * NN_;
    #pragma unroll
    for (int u = 0; u < 8; u++)
        #pragma unroll
        for (int v = 0; v < 8; v++)
            po[(bb + 16*u) * N_ + (jj + 16*v)] = a[u][v];
}

// ---------------- raw reduce: grid 128, float4, 8-way ks split ----------------
__global__ void k_rawred(const float4* __restrict__ part4, float4* __restrict__ raw4) {
    __shared__ float4 red[8][32];
    const int g  = threadIdx.x >> 5;                  // ks group 0..7 (16 ks each)
    const int o4 = threadIdx.x & 31;                  // output float4 within block
    const int oi = (blockIdx.x << 5) + o4;            // 0..4095
    float4 s = make_float4(0.f, 0.f, 0.f, 0.f);
    #pragma unroll
    for (int ks = g * 16; ks < g * 16 + 16; ks++) {
        float4 v = part4[(size_t)ks * (NN_ / 4) + oi];
        s.x += v.x; s.y += v.y; s.z += v.z; s.w += v.w;
    }
    red[g][o4] = s;
    __syncthreads();
    if (threadIdx.x < 32) {
        float4 t = make_float4(0.f, 0.f, 0.f, 0.f);
        #pragma unroll
        for (int q = 0; q < 8; q += 2) {
            float4 a = red[q][threadIdx.x], b = red[q + 1][threadIdx.x];
            t.x += a.x + b.x; t.y += a.y + b.y;
            t.z += a.z + b.z; t.w += a.w + b.w;
        }
        raw4[(blockIdx.x << 5) + threadIdx.x] = t;
    }
}

// ---------------- launch ----------------
extern "C" void kernel_launch(void* const* d_in, const int* in_sizes, int n_in,
                              void* d_out, int out_size) {
    const float* x   = (const float*)d_in[0];
    const float* rs  = (const float*)d_in[1];
    const float* Wc  = (const float*)d_in[2];
    const float* bc  = (const float*)d_in[3];
    const float* Ww  = (const float*)d_in[4];
    const float* bw  = (const float*)d_in[5];
    const float* adj = (const float*)d_in[6];
    float* out = (float*)d_out;

    __nv_bfloat16 *p_meanbf, *p_ctxbf;
    float *p_ctxp, *p_part, *p_raw;
    cudaGetSymbolAddress((void**)&p_meanbf, g_meanbf);
    cudaGetSymbolAddress((void**)&p_ctxbf, g_ctxbf);
    cudaGetSymbolAddress((void**)&p_ctxp,  g_ctxp);
    cudaGetSymbolAddress((void**)&p_part,  g_part);
    cudaGetSymbolAddress((void**)&p_raw,   g_raw);

    // 1. mean over S (HBM-bound, 512 MB) -> bf16
    k_mean<<<B_ * 8, 64>>>((const float4*)x, (uint2*)p_meanbf);

    // 2. context partials: split-K x2, 128 blocks, warps 4x2
    {
        size_t sh = (size_t)STG * (ATB + 32 * BPAD * 4);
        cudaFuncSetAttribute((const void*)k_gemm<32, D_, 0, 4, 2>,
                             cudaFuncAttributeMaxDynamicSharedMemorySize, (int)sh);
        k_gemm<32, D_, 0, 4, 2><<<128, 256, sh>>>(p_meanbf, Wc, nullptr, p_ctxp,
                                                  nullptr, nullptr);
    }

    // 3. fused: ctx = p0+p1+bc (-> bf16) + raw split-K partials; then reduce
    k_rawctx<<<128, 256>>>(p_ctxp, bc, rs, p_part, p_ctxbf);
    k_rawred<<<128, 256>>>((const float4*)p_part, (float4*)p_raw);

    // 4+5. warp GEMM + fused softmax/einsum/sigmoid, warps 2x4
    {
        size_t stages = (size_t)STG * (ATB + 128 * BPAD * 4);          // 221,184 B
        size_t epi    = (size_t)(128 * 130 + 128 * 129) * 4;           // 132,608 B
        size_t sh     = stages > epi ? stages : epi;
        cudaFuncSetAttribute((const void*)k_gemm<128, NN_, 3, 2, 4>,
                             cudaFuncAttributeMaxDynamicSharedMemorySize, (int)sh);
        k_gemm<128, NN_, 3, 2, 4><<<128, 256, sh>>>(p_ctxbf, Ww, bw, out, adj, p_raw);
    }
}